// round 1
// baseline (speedup 1.0000x reference)
#include <cuda_runtime.h>
#include <cuda_bf16.h>

#define BB 2
#define TT 2048
#define EE 1024
#define HH 16
#define DH 64
#define MTOT (BB*TT)   // 4096

// Scratch (allocation-free rule: __device__ globals)
__device__ float g_Q[(size_t)BB*HH*TT*DH];
__device__ float g_K[(size_t)BB*HH*TT*DH];
__device__ float g_V[(size_t)BB*HH*TT*DH];
__device__ float g_A[(size_t)BB*TT*EE];

// ---------------------------------------------------------------------------
// Kernel 1: QKV projection. grid = (H, MTOT/64, 3), block = 256.
// out[b,h,t,d] = sum_e x[b,t,e] * W[h,e,d]
// ---------------------------------------------------------------------------
__global__ __launch_bounds__(256) void qkv_kernel(
    const float* __restrict__ x, const float* __restrict__ Wq,
    const float* __restrict__ Wk, const float* __restrict__ Wv) {
  const int h  = blockIdx.x;
  const int m0 = blockIdx.y * 64;
  const float* W;
  float* out;
  if (blockIdx.z == 0)      { W = Wq; out = g_Q; }
  else if (blockIdx.z == 1) { W = Wk; out = g_K; }
  else                      { W = Wv; out = g_V; }
  W += (size_t)h * EE * DH;

  __shared__ __align__(16) float As[16][68];  // [k][m]
  __shared__ __align__(16) float Bs[16][68];  // [k][n]

  const int tid = threadIdx.x;
  const int tx = tid & 15, ty = tid >> 4;
  float acc[4][4] = {};

  for (int k0 = 0; k0 < EE; k0 += 16) {
    #pragma unroll
    for (int i = tid; i < 64*16; i += 256) {
      int row = i >> 4, kk = i & 15;
      As[kk][row] = x[(size_t)(m0 + row) * EE + k0 + kk];
    }
    #pragma unroll
    for (int i = tid; i < 16*64; i += 256) {
      int kk = i >> 6, d = i & 63;
      Bs[kk][d] = W[(size_t)(k0 + kk) * DH + d];
    }
    __syncthreads();
    #pragma unroll
    for (int kk = 0; kk < 16; kk++) {
      float4 a4 = *(const float4*)&As[kk][ty*4];
      float4 b4 = *(const float4*)&Bs[kk][tx*4];
      float av[4] = {a4.x, a4.y, a4.z, a4.w};
      float bv[4] = {b4.x, b4.y, b4.z, b4.w};
      #pragma unroll
      for (int ii = 0; ii < 4; ii++)
        #pragma unroll
        for (int jj = 0; jj < 4; jj++)
          acc[ii][jj] += av[ii] * bv[jj];
    }
    __syncthreads();
  }
  #pragma unroll
  for (int ii = 0; ii < 4; ii++) {
    int m = m0 + ty*4 + ii;
    int b = m / TT, t = m % TT;
    float4 st = make_float4(acc[ii][0], acc[ii][1], acc[ii][2], acc[ii][3]);
    *(float4*)&out[(((size_t)b*HH + h)*TT + t)*DH + tx*4] = st;
  }
}

// ---------------------------------------------------------------------------
// Kernel 2: causal flash attention. grid = (TT/64, BB*HH), block = 256.
// Each block: 64 query rows of one (b,h). Online softmax, P staged via smem.
// ---------------------------------------------------------------------------
#define TILE_F (64*68)
#define ATT_SMEM (4 * TILE_F * 4)   // 69632 bytes

__global__ __launch_bounds__(256) void attn_kernel() {
  extern __shared__ __align__(16) float sm[];
  float (*Qt)[68] = (float(*)[68])(sm);              // [d][q]  (d-major)
  float (*Kt)[68] = (float(*)[68])(sm + TILE_F);     // [d][key]
  float (*Vs)[68] = (float(*)[68])(sm + 2*TILE_F);   // [key][d]
  float (*Ps)[68] = (float(*)[68])(sm + 3*TILE_F);   // [q][key]

  const int i0 = blockIdx.x * 64;
  const int bh = blockIdx.y;
  const int b = bh >> 4, h = bh & 15;
  const float* Qb = g_Q + (size_t)bh * TT * DH;
  const float* Kb = g_K + (size_t)bh * TT * DH;
  const float* Vb = g_V + (size_t)bh * TT * DH;

  const int tid = threadIdx.x;
  const int tx = tid & 15, ty = tid >> 4;

  // Load Q tile transposed, scale folded in (1/sqrt(64) = 0.125)
  for (int i = tid; i < 64*64; i += 256) {
    int r = i >> 6, d = i & 63;
    Qt[d][r] = Qb[(size_t)(i0 + r) * DH + d] * 0.125f;
  }

  float m_i[4], l_i[4], O[4][4];
  #pragma unroll
  for (int ii = 0; ii < 4; ii++) {
    m_i[ii] = -1e30f; l_i[ii] = 0.f;
    #pragma unroll
    for (int jj = 0; jj < 4; jj++) O[ii][jj] = 0.f;
  }

  for (int j0 = 0; j0 <= i0; j0 += 64) {
    __syncthreads();  // protect Kt/Vs/Ps from previous iteration
    for (int i = tid; i < 64*64; i += 256) {
      int r = i >> 6, d = i & 63;
      float kv = Kb[(size_t)(j0 + r) * DH + d];
      float vv = Vb[(size_t)(j0 + r) * DH + d];
      Kt[d][r] = kv;
      Vs[r][d] = vv;
    }
    __syncthreads();

    // S = Q K^T  (reduction over d)
    float s[4][4] = {};
    #pragma unroll 8
    for (int d = 0; d < 64; d++) {
      float4 q4 = *(const float4*)&Qt[d][ty*4];
      float4 k4 = *(const float4*)&Kt[d][tx*4];
      float qv[4] = {q4.x, q4.y, q4.z, q4.w};
      float kv[4] = {k4.x, k4.y, k4.z, k4.w};
      #pragma unroll
      for (int ii = 0; ii < 4; ii++)
        #pragma unroll
        for (int jj = 0; jj < 4; jj++)
          s[ii][jj] += qv[ii] * kv[jj];
    }

    // Causal mask only needed on the diagonal block
    if (j0 == i0) {
      #pragma unroll
      for (int ii = 0; ii < 4; ii++)
        #pragma unroll
        for (int jj = 0; jj < 4; jj++)
          if (tx*4 + jj > ty*4 + ii) s[ii][jj] = -1e30f;
    }

    // Online softmax (row group = 16 consecutive lanes -> width-16 shuffles)
    #pragma unroll
    for (int ii = 0; ii < 4; ii++) {
      float mx = fmaxf(fmaxf(s[ii][0], s[ii][1]), fmaxf(s[ii][2], s[ii][3]));
      #pragma unroll
      for (int off = 8; off > 0; off >>= 1)
        mx = fmaxf(mx, __shfl_xor_sync(0xffffffffu, mx, off, 16));
      float mnew  = fmaxf(m_i[ii], mx);
      float alpha = __expf(m_i[ii] - mnew);
      m_i[ii] = mnew;
      float ls = 0.f;
      #pragma unroll
      for (int jj = 0; jj < 4; jj++) {
        float p = __expf(s[ii][jj] - mnew);
        s[ii][jj] = p;
        ls += p;
      }
      #pragma unroll
      for (int off = 8; off > 0; off >>= 1)
        ls += __shfl_xor_sync(0xffffffffu, ls, off, 16);
      l_i[ii] = l_i[ii] * alpha + ls;
      #pragma unroll
      for (int jj = 0; jj < 4; jj++) O[ii][jj] *= alpha;
    }

    // Stage P, then O += P V  (reduction over keys)
    #pragma unroll
    for (int ii = 0; ii < 4; ii++) {
      float4 st = make_float4(s[ii][0], s[ii][1], s[ii][2], s[ii][3]);
      *(float4*)&Ps[ty*4 + ii][tx*4] = st;
    }
    __syncthreads();
    #pragma unroll 4
    for (int c = 0; c < 64; c++) {
      float4 v4 = *(const float4*)&Vs[c][tx*4];
      float vv[4] = {v4.x, v4.y, v4.z, v4.w};
      #pragma unroll
      for (int ii = 0; ii < 4; ii++) {
        float p = Ps[ty*4 + ii][c];
        #pragma unroll
        for (int jj = 0; jj < 4; jj++)
          O[ii][jj] += p * vv[jj];
      }
    }
  }

  // Epilogue: normalize, write concat-head layout g_A[b][t][h*64 + d]
  #pragma unroll
  for (int ii = 0; ii < 4; ii++) {
    float inv = 1.f / l_i[ii];
    int t = i0 + ty*4 + ii;
    float4 st = make_float4(O[ii][0]*inv, O[ii][1]*inv, O[ii][2]*inv, O[ii][3]*inv);
    *(float4*)&g_A[((size_t)b*TT + t)*EE + h*DH + tx*4] = st;
  }
}

// ---------------------------------------------------------------------------
// Kernel 3: output projection  out = A @ Wo^T + bias. grid = (EE/64, MTOT/64).
// Wo is [out=E][in=E] row-major (torch Linear weight).
// ---------------------------------------------------------------------------
__global__ __launch_bounds__(256) void oproj_kernel(
    const float* __restrict__ Wo, const float* __restrict__ bias,
    float* __restrict__ out) {
  const int n0 = blockIdx.x * 64;
  const int m0 = blockIdx.y * 64;

  __shared__ __align__(16) float As[16][68];
  __shared__ __align__(16) float Bs[16][68];

  const int tid = threadIdx.x;
  const int tx = tid & 15, ty = tid >> 4;
  float acc[4][4] = {};

  for (int k0 = 0; k0 < EE; k0 += 16) {
    #pragma unroll
    for (int i = tid; i < 64*16; i += 256) {
      int row = i >> 4, kk = i & 15;
      As[kk][row] = g_A[(size_t)(m0 + row) * EE + k0 + kk];
    }
    #pragma unroll
    for (int i = tid; i < 64*16; i += 256) {
      int n = i >> 4, kk = i & 15;
      Bs[kk][n] = Wo[(size_t)(n0 + n) * EE + k0 + kk];
    }
    __syncthreads();
    #pragma unroll
    for (int kk = 0; kk < 16; kk++) {
      float4 a4 = *(const float4*)&As[kk][ty*4];
      float4 b4 = *(const float4*)&Bs[kk][tx*4];
      float av[4] = {a4.x, a4.y, a4.z, a4.w};
      float bv[4] = {b4.x, b4.y, b4.z, b4.w};
      #pragma unroll
      for (int ii = 0; ii < 4; ii++)
        #pragma unroll
        for (int jj = 0; jj < 4; jj++)
          acc[ii][jj] += av[ii] * bv[jj];
    }
    __syncthreads();
  }

  float4 bv4 = *(const float4*)&bias[n0 + tx*4];
  float bvv[4] = {bv4.x, bv4.y, bv4.z, bv4.w};
  #pragma unroll
  for (int ii = 0; ii < 4; ii++) {
    int m = m0 + ty*4 + ii;
    float4 st = make_float4(acc[ii][0] + bvv[0], acc[ii][1] + bvv[1],
                            acc[ii][2] + bvv[2], acc[ii][3] + bvv[3]);
    *(float4*)&out[(size_t)m * EE + n0 + tx*4] = st;
  }
}

// ---------------------------------------------------------------------------
extern "C" void kernel_launch(void* const* d_in, const int* in_sizes, int n_in,
                              void* d_out, int out_size) {
  const float* x  = (const float*)d_in[0];
  const float* Wq = (const float*)d_in[1];
  const float* Wk = (const float*)d_in[2];
  const float* Wv = (const float*)d_in[3];
  const float* Wo = (const float*)d_in[4];
  const float* wb = (const float*)d_in[5];
  float* out = (float*)d_out;

  qkv_kernel<<<dim3(HH, MTOT/64, 3), 256>>>(x, Wq, Wk, Wv);

  cudaFuncSetAttribute(attn_kernel,
                       cudaFuncAttributeMaxDynamicSharedMemorySize, ATT_SMEM);
  attn_kernel<<<dim3(TT/64, BB*HH), 256, ATT_SMEM>>>();

  oproj_kernel<<<dim3(EE/64, MTOT/64), 256>>>(Wo, wb, out);
}

// round 3
// speedup vs baseline: 1.2331x; 1.2331x over previous
#include <cuda_runtime.h>
#include <cuda_bf16.h>
#include <cstdint>

#define BB 2
#define TT 2048
#define EE 1024
#define HH 16
#define DH 64
#define MTOT (BB*TT)   // 4096

// Scratch (allocation-free rule: __device__ globals)
__device__ float g_Q[(size_t)BB*HH*TT*DH];
__device__ float g_K[(size_t)BB*HH*TT*DH];
__device__ float g_V[(size_t)BB*HH*TT*DH];
__device__ float g_A[(size_t)BB*TT*EE];
__device__ float g_Wt[(size_t)3*HH*DH*EE];   // [3072][1024] K-major fused QKV weights

// ---------------------------------------------------------------------------
// Helpers
// ---------------------------------------------------------------------------
__device__ __forceinline__ uint32_t smem_u32(const void* p) {
  uint32_t a;
  asm("{ .reg .u64 t; cvta.to.shared.u64 t, %1; cvt.u32.u64 %0, t; }" : "=r"(a) : "l"(p));
  return a;
}
__device__ __forceinline__ uint32_t lds32(uint32_t a) {
  uint32_t v;
  asm volatile("ld.shared.b32 %0, [%1];" : "=r"(v) : "r"(a));
  return v;
}
// SW128 swizzle for 128-byte rows: XOR bits[6:4] with bits[9:7]
__device__ __forceinline__ uint32_t swz(int r, int cfloat) {
  uint32_t b = (uint32_t)(r * 128 + cfloat * 4);
  return b ^ ((b >> 3) & 0x70);
}
__device__ __forceinline__ void tf32_split(float x, uint32_t& hi, uint32_t& lo) {
  uint32_t h;
  asm("cvt.rna.tf32.f32 %0, %1;" : "=r"(h) : "f"(x));
  float hf = __uint_as_float(h);
  float lf = x - hf;                 // exact (fits in fp32)
  uint32_t l;
  asm("cvt.rna.tf32.f32 %0, %1;" : "=r"(l) : "f"(lf));
  hi = h; lo = l;
}
__device__ __forceinline__ void mma_tf32_16n8k8(float c[4], uint32_t a0, uint32_t a1,
                                                uint32_t a2, uint32_t a3,
                                                uint32_t b0, uint32_t b1) {
  asm volatile(
    "mma.sync.aligned.m16n8k8.row.col.f32.tf32.tf32.f32 "
    "{%0,%1,%2,%3}, {%4,%5,%6,%7}, {%8,%9}, {%0,%1,%2,%3};"
    : "+f"(c[0]), "+f"(c[1]), "+f"(c[2]), "+f"(c[3])
    : "r"(a0), "r"(a1), "r"(a2), "r"(a3), "r"(b0), "r"(b1));
}

// ---------------------------------------------------------------------------
// Weight transpose: g_Wt[(p*16+h)*64 + d][e] = W_p[h][e][d]
// ---------------------------------------------------------------------------
__global__ __launch_bounds__(256) void transpose_w(
    const float* __restrict__ Wq, const float* __restrict__ Wk,
    const float* __restrict__ Wv) {
  __shared__ float t[32][33];
  const int bz = blockIdx.z;             // 0..47 = p*16+h
  const int p = bz >> 4;
  const float* W = (p == 0 ? Wq : p == 1 ? Wk : Wv) + (size_t)(bz & 15) * EE * DH;
  const int e0 = blockIdx.x * 32;
  const int d0 = blockIdx.y * 32;
  const int tx = threadIdx.x, ty = threadIdx.y;
  #pragma unroll
  for (int i = ty; i < 32; i += 8)
    t[i][tx] = W[(size_t)(e0 + i) * DH + d0 + tx];
  __syncthreads();
  float* out = g_Wt + (size_t)bz * DH * EE;
  #pragma unroll
  for (int i = ty; i < 32; i += 8)
    out[(size_t)(d0 + i) * EE + e0 + tx] = t[tx][i];
}

// ---------------------------------------------------------------------------
// 3-pass tf32 HMMA GEMM (error ~= fp32). BM=128, BN=128, BK=32, 256 threads.
// C[m][n] = sum_k A[m][k]*B[n][k]   (both operands K-major, stride EE)
// MODE 0: A = x [4096,1024], B = g_Wt [3072,1024] -> scatter into g_Q/g_K/g_V
// MODE 1: A = g_A [4096,1024], B = Wo [1024,1024] -> d_out + bias
// smem per stage: Ah/Al/Bh/Bl tiles, 16KB each -> 64KB; 2 stages = 128KB.
// ---------------------------------------------------------------------------
#define BK 32
#define NKIT (EE / BK)          // 32
#define TILE_B 16384            // one 128x32 fp32 tile
#define STG_B  (4 * TILE_B)     // 65536
#define GEMM_SMEM (2 * STG_B)   // 131072

template<int MODE>
__global__ __launch_bounds__(256) void gemm3p(
    const float* __restrict__ Ain, const float* __restrict__ Bin,
    const float* __restrict__ bias, float* __restrict__ outp) {
  extern __shared__ __align__(128) char dsm[];
  const float* A = (MODE == 0) ? Ain : (const float*)g_A;
  const float* B = (MODE == 0) ? (const float*)g_Wt : Bin;

  const int tid = threadIdx.x;
  const int lane = tid & 31;
  const int g  = lane >> 2;        // 0..7
  const int tg = lane & 3;         // 0..3
  const int wid = tid >> 5;
  const int wm = wid >> 2;         // 0..1
  const int wn = wid & 3;          // 0..3

  const size_t m0 = (size_t)blockIdx.y * 128;
  const int n0 = blockIdx.x * 128;
  const uint32_t s0 = smem_u32(dsm);

  // per-thread load slots: idx = tid + j*256; r = idx>>3 (row), c4 = idx&7 (float4 col)
  float4 ra[4], rb[4];
  #pragma unroll
  for (int j = 0; j < 4; j++) {
    const int idx = tid + j * 256;
    const int r = idx >> 3, c4 = idx & 7;
    ra[j] = *(const float4*)(A + (m0 + r) * EE + c4 * 4);
    rb[j] = *(const float4*)(B + (size_t)(n0 + r) * EE + c4 * 4);
  }

  float C[4][4][4];
  #pragma unroll
  for (int a = 0; a < 4; a++)
    #pragma unroll
    for (int b = 0; b < 4; b++)
      #pragma unroll
      for (int c = 0; c < 4; c++) C[a][b][c] = 0.f;

  for (int i = 0; i < NKIT; i++) {
    const uint32_t st = s0 + (uint32_t)(i & 1) * STG_B;
    const uint32_t Ah = st, Al = st + TILE_B, Bh = st + 2*TILE_B, Bl = st + 3*TILE_B;

    // split + store staged registers
    #pragma unroll
    for (int j = 0; j < 4; j++) {
      const int idx = tid + j * 256;
      const int r = idx >> 3, c4 = idx & 7;
      const uint32_t off = swz(r, c4 * 4);
      uint32_t h0,h1,h2,h3, l0,l1,l2,l3;
      tf32_split(ra[j].x, h0, l0); tf32_split(ra[j].y, h1, l1);
      tf32_split(ra[j].z, h2, l2); tf32_split(ra[j].w, h3, l3);
      asm volatile("st.shared.v4.b32 [%0], {%1,%2,%3,%4};" :: "r"(Ah + off), "r"(h0),"r"(h1),"r"(h2),"r"(h3) : "memory");
      asm volatile("st.shared.v4.b32 [%0], {%1,%2,%3,%4};" :: "r"(Al + off), "r"(l0),"r"(l1),"r"(l2),"r"(l3) : "memory");
      tf32_split(rb[j].x, h0, l0); tf32_split(rb[j].y, h1, l1);
      tf32_split(rb[j].z, h2, l2); tf32_split(rb[j].w, h3, l3);
      asm volatile("st.shared.v4.b32 [%0], {%1,%2,%3,%4};" :: "r"(Bh + off), "r"(h0),"r"(h1),"r"(h2),"r"(h3) : "memory");
      asm volatile("st.shared.v4.b32 [%0], {%1,%2,%3,%4};" :: "r"(Bl + off), "r"(l0),"r"(l1),"r"(l2),"r"(l3) : "memory");
    }
    __syncthreads();

    // prefetch next k-slab into registers (overlaps with MMA below)
    if (i + 1 < NKIT) {
      const int k0 = (i + 1) * BK;
      #pragma unroll
      for (int j = 0; j < 4; j++) {
        const int idx = tid + j * 256;
        const int r = idx >> 3, c4 = idx & 7;
        ra[j] = *(const float4*)(A + (m0 + r) * EE + k0 + c4 * 4);
        rb[j] = *(const float4*)(B + (size_t)(n0 + r) * EE + k0 + c4 * 4);
      }
    }

    // compute on this stage
    #pragma unroll
    for (int ks = 0; ks < 4; ks++) {
      const int kc = ks * 8;
      uint32_t ah[4][4], al[4][4];
      #pragma unroll
      for (int mt = 0; mt < 4; mt++) {
        const int r0 = wm * 64 + mt * 16 + g;
        ah[mt][0] = lds32(Ah + swz(r0,     kc + tg));
        ah[mt][1] = lds32(Ah + swz(r0 + 8, kc + tg));
        ah[mt][2] = lds32(Ah + swz(r0,     kc + tg + 4));
        ah[mt][3] = lds32(Ah + swz(r0 + 8, kc + tg + 4));
        al[mt][0] = lds32(Al + swz(r0,     kc + tg));
        al[mt][1] = lds32(Al + swz(r0 + 8, kc + tg));
        al[mt][2] = lds32(Al + swz(r0,     kc + tg + 4));
        al[mt][3] = lds32(Al + swz(r0 + 8, kc + tg + 4));
      }
      #pragma unroll
      for (int nt = 0; nt < 4; nt++) {
        const int n = wn * 32 + nt * 8 + g;
        const uint32_t bh0 = lds32(Bh + swz(n, kc + tg));
        const uint32_t bh1 = lds32(Bh + swz(n, kc + tg + 4));
        const uint32_t bl0 = lds32(Bl + swz(n, kc + tg));
        const uint32_t bl1 = lds32(Bl + swz(n, kc + tg + 4));
        #pragma unroll
        for (int mt = 0; mt < 4; mt++) {
          mma_tf32_16n8k8(C[mt][nt], ah[mt][0], ah[mt][1], ah[mt][2], ah[mt][3], bh0, bh1);
          mma_tf32_16n8k8(C[mt][nt], ah[mt][0], ah[mt][1], ah[mt][2], ah[mt][3], bl0, bl1);
          mma_tf32_16n8k8(C[mt][nt], al[mt][0], al[mt][1], al[mt][2], al[mt][3], bh0, bh1);
        }
      }
    }
    __syncthreads();
  }

  // epilogue
  #pragma unroll
  for (int mt = 0; mt < 4; mt++) {
    const size_t r0 = m0 + wm * 64 + mt * 16 + g;
    #pragma unroll
    for (int nt = 0; nt < 4; nt++) {
      const int col = n0 + wn * 32 + nt * 8 + 2 * tg;
      if (MODE == 0) {
        const int p = col >> 10;
        const int rl = col & 1023;
        const int h = rl >> 6, d0 = rl & 63;
        float* ob = (p == 0) ? g_Q : (p == 1) ? g_K : g_V;
        const int b = (int)(r0 >> 11);
        const int t = (int)(r0 & (TT - 1));
        float* base = ob + (((size_t)b * HH + h) * TT) * DH + d0;
        *(float2*)(base + (size_t)t * DH)       = make_float2(C[mt][nt][0], C[mt][nt][1]);
        *(float2*)(base + (size_t)(t + 8) * DH) = make_float2(C[mt][nt][2], C[mt][nt][3]);
      } else {
        const float2 bv = *(const float2*)(bias + col);
        *(float2*)(outp + r0 * EE + col) =
            make_float2(C[mt][nt][0] + bv.x, C[mt][nt][1] + bv.y);
        *(float2*)(outp + (r0 + 8) * EE + col) =
            make_float2(C[mt][nt][2] + bv.x, C[mt][nt][3] + bv.y);
      }
    }
  }
}

// ---------------------------------------------------------------------------
// Causal flash attention (fp32 CUDA-core, unchanged). grid = (TT/64, BB*HH).
// ---------------------------------------------------------------------------
#define TILE_F (64*68)
#define ATT_SMEM (4 * TILE_F * 4)   // 69632 bytes

__global__ __launch_bounds__(256) void attn_kernel() {
  extern __shared__ __align__(16) float sm[];
  float (*Qt)[68] = (float(*)[68])(sm);              // [d][q]
  float (*Kt)[68] = (float(*)[68])(sm + TILE_F);     // [d][key]
  float (*Vs)[68] = (float(*)[68])(sm + 2*TILE_F);   // [key][d]
  float (*Ps)[68] = (float(*)[68])(sm + 3*TILE_F);   // [q][key]

  const int i0 = blockIdx.x * 64;
  const int bh = blockIdx.y;
  const int b = bh >> 4, h = bh & 15;
  const float* Qb = g_Q + (size_t)bh * TT * DH;
  const float* Kb = g_K + (size_t)bh * TT * DH;
  const float* Vb = g_V + (size_t)bh * TT * DH;

  const int tid = threadIdx.x;
  const int tx = tid & 15, ty = tid >> 4;

  for (int i = tid; i < 64*64; i += 256) {
    int r = i >> 6, d = i & 63;
    Qt[d][r] = Qb[(size_t)(i0 + r) * DH + d] * 0.125f;
  }

  float m_i[4], l_i[4], O[4][4];
  #pragma unroll
  for (int ii = 0; ii < 4; ii++) {
    m_i[ii] = -1e30f; l_i[ii] = 0.f;
    #pragma unroll
    for (int jj = 0; jj < 4; jj++) O[ii][jj] = 0.f;
  }

  for (int j0 = 0; j0 <= i0; j0 += 64) {
    __syncthreads();
    for (int i = tid; i < 64*64; i += 256) {
      int r = i >> 6, d = i & 63;
      Kt[d][r] = Kb[(size_t)(j0 + r) * DH + d];
      Vs[r][d] = Vb[(size_t)(j0 + r) * DH + d];
    }
    __syncthreads();

    float s[4][4] = {};
    #pragma unroll 8
    for (int d = 0; d < 64; d++) {
      float4 q4 = *(const float4*)&Qt[d][ty*4];
      float4 k4 = *(const float4*)&Kt[d][tx*4];
      float qv[4] = {q4.x, q4.y, q4.z, q4.w};
      float kv[4] = {k4.x, k4.y, k4.z, k4.w};
      #pragma unroll
      for (int ii = 0; ii < 4; ii++)
        #pragma unroll
        for (int jj = 0; jj < 4; jj++)
          s[ii][jj] += qv[ii] * kv[jj];
    }

    if (j0 == i0) {
      #pragma unroll
      for (int ii = 0; ii < 4; ii++)
        #pragma unroll
        for (int jj = 0; jj < 4; jj++)
          if (tx*4 + jj > ty*4 + ii) s[ii][jj] = -1e30f;
    }

    #pragma unroll
    for (int ii = 0; ii < 4; ii++) {
      float mx = fmaxf(fmaxf(s[ii][0], s[ii][1]), fmaxf(s[ii][2], s[ii][3]));
      #pragma unroll
      for (int off = 8; off > 0; off >>= 1)
        mx = fmaxf(mx, __shfl_xor_sync(0xffffffffu, mx, off, 16));
      float mnew  = fmaxf(m_i[ii], mx);
      float alpha = __expf(m_i[ii] - mnew);
      m_i[ii] = mnew;
      float ls = 0.f;
      #pragma unroll
      for (int jj = 0; jj < 4; jj++) {
        float p = __expf(s[ii][jj] - mnew);
        s[ii][jj] = p;
        ls += p;
      }
      #pragma unroll
      for (int off = 8; off > 0; off >>= 1)
        ls += __shfl_xor_sync(0xffffffffu, ls, off, 16);
      l_i[ii] = l_i[ii] * alpha + ls;
      #pragma unroll
      for (int jj = 0; jj < 4; jj++) O[ii][jj] *= alpha;
    }

    #pragma unroll
    for (int ii = 0; ii < 4; ii++) {
      float4 st = make_float4(s[ii][0], s[ii][1], s[ii][2], s[ii][3]);
      *(float4*)&Ps[ty*4 + ii][tx*4] = st;
    }
    __syncthreads();
    #pragma unroll 4
    for (int c = 0; c < 64; c++) {
      float4 v4 = *(const float4*)&Vs[c][tx*4];
      float vv[4] = {v4.x, v4.y, v4.z, v4.w};
      #pragma unroll
      for (int ii = 0; ii < 4; ii++) {
        float p = Ps[ty*4 + ii][c];
        #pragma unroll
        for (int jj = 0; jj < 4; jj++)
          O[ii][jj] += p * vv[jj];
      }
    }
  }

  #pragma unroll
  for (int ii = 0; ii < 4; ii++) {
    float inv = 1.f / l_i[ii];
    int t = i0 + ty*4 + ii;
    float4 st = make_float4(O[ii][0]*inv, O[ii][1]*inv, O[ii][2]*inv, O[ii][3]*inv);
    *(float4*)&g_A[((size_t)b*TT + t)*EE + h*DH + tx*4] = st;
  }
}

// ---------------------------------------------------------------------------
extern "C" void kernel_launch(void* const* d_in, const int* in_sizes, int n_in,
                              void* d_out, int out_size) {
  const float* x  = (const float*)d_in[0];
  const float* Wq = (const float*)d_in[1];
  const float* Wk = (const float*)d_in[2];
  const float* Wv = (const float*)d_in[3];
  const float* Wo = (const float*)d_in[4];
  const float* wb = (const float*)d_in[5];
  float* out = (float*)d_out;

  cudaFuncSetAttribute(gemm3p<0>, cudaFuncAttributeMaxDynamicSharedMemorySize, GEMM_SMEM);
  cudaFuncSetAttribute(gemm3p<1>, cudaFuncAttributeMaxDynamicSharedMemorySize, GEMM_SMEM);
  cudaFuncSetAttribute(attn_kernel, cudaFuncAttributeMaxDynamicSharedMemorySize, ATT_SMEM);

  transpose_w<<<dim3(EE/32, DH/32, 48), dim3(32, 8)>>>(Wq, Wk, Wv);

  gemm3p<0><<<dim3(3072/128, MTOT/128), 256, GEMM_SMEM>>>(x, nullptr, nullptr, nullptr);

  attn_kernel<<<dim3(TT/64, BB*HH), 256, ATT_SMEM>>>();

  gemm3p<1><<<dim3(EE/128, MTOT/128), 256, GEMM_SMEM>>>(nullptr, Wo, wb, out);
}

// round 5
// speedup vs baseline: 2.4403x; 1.9790x over previous
#include <cuda_runtime.h>
#include <cuda_fp16.h>
#include <cstdint>

#define BB 2
#define TT 2048
#define EE 1024
#define HH 16
#define DH 64
#define MTOT (BB*TT)   // 4096
#define BHN (BB*HH)    // 32

// ---------------------------------------------------------------------------
// Global scratch (allocation-free rule): fp16 hi/lo split arrays
// 128B-aligned: cp.async 16B ops require aligned global addresses.
// ---------------------------------------------------------------------------
__device__ __align__(128) __half g_xh[(size_t)MTOT*EE];
__device__ __align__(128) __half g_xl[(size_t)MTOT*EE];
__device__ __align__(128) __half g_Wth[(size_t)3*EE*EE];   // [3072][1024]
__device__ __align__(128) __half g_Wtl[(size_t)3*EE*EE];
__device__ __align__(128) __half g_Qh[(size_t)BHN*TT*DH];  // [bh][t][d]
__device__ __align__(128) __half g_Ql[(size_t)BHN*TT*DH];
__device__ __align__(128) __half g_Kh[(size_t)BHN*TT*DH];  // [bh][t][d]
__device__ __align__(128) __half g_Kl[(size_t)BHN*TT*DH];
__device__ __align__(128) __half g_Vth[(size_t)BHN*TT*DH]; // [bh][d][t]
__device__ __align__(128) __half g_Vtl[(size_t)BHN*TT*DH];
__device__ __align__(128) __half g_Ah[(size_t)MTOT*EE];    // attn out
__device__ __align__(128) __half g_Al[(size_t)MTOT*EE];
__device__ __align__(128) __half g_Woh[(size_t)EE*EE];     // [out][in]
__device__ __align__(128) __half g_Wol[(size_t)EE*EE];

// ---------------------------------------------------------------------------
// Helpers
// ---------------------------------------------------------------------------
__device__ __forceinline__ uint32_t smem_u32(const void* p) {
  uint32_t a;
  asm("{ .reg .u64 t; cvta.to.shared.u64 t, %1; cvt.u32.u64 %0, t; }" : "=r"(a) : "l"(p));
  return a;
}
__device__ __forceinline__ uint32_t lds32(uint32_t a) {
  uint32_t v;
  asm volatile("ld.shared.b32 %0, [%1];" : "=r"(v) : "r"(a));
  return v;
}
__device__ __forceinline__ void cp16(uint32_t dst, const void* src) {
  asm volatile("cp.async.ca.shared.global [%0], [%1], 16;" :: "r"(dst), "l"(src) : "memory");
}
__device__ __forceinline__ void cp_commit() {
  asm volatile("cp.async.commit_group;" ::: "memory");
}
template<int N> __device__ __forceinline__ void cp_wait() {
  asm volatile("cp.async.wait_group %0;" :: "n"(N) : "memory");
}
__device__ __forceinline__ void f16_split(float x, __half& h, __half& l) {
  h = __float2half_rn(x);
  l = __float2half_rn(x - __half2float(h));
}
__device__ __forceinline__ void store_split(__half* H, __half* L, size_t idx, float v) {
  __half h, l; f16_split(v, h, l);
  H[idx] = h; L[idx] = l;
}
// pack two floats into (hi-pair, lo-pair) b32 half2 regs; a -> low half
__device__ __forceinline__ void split2(float a, float b, uint32_t& hi, uint32_t& lo) {
  __half ha, la, hb, lb;
  f16_split(a, ha, la); f16_split(b, hb, lb);
  __half2 H = __halves2half2(ha, hb), L = __halves2half2(la, lb);
  hi = *(uint32_t*)&H; lo = *(uint32_t*)&L;
}
__device__ __forceinline__ void mma_f16(float c[4], uint32_t a0, uint32_t a1,
                                        uint32_t a2, uint32_t a3,
                                        uint32_t b0, uint32_t b1) {
  asm volatile(
    "mma.sync.aligned.m16n8k16.row.col.f32.f16.f16.f32 "
    "{%0,%1,%2,%3},{%4,%5,%6,%7},{%8,%9},{%0,%1,%2,%3};"
    : "+f"(c[0]), "+f"(c[1]), "+f"(c[2]), "+f"(c[3])
    : "r"(a0), "r"(a1), "r"(a2), "r"(a3), "r"(b0), "r"(b1));
}

// ---------------------------------------------------------------------------
// Pre-split: fp32 -> (hi, lo) halves. n multiple of 4.
// ---------------------------------------------------------------------------
__global__ __launch_bounds__(256) void split_f32(const float* __restrict__ s,
                                                 __half* __restrict__ H,
                                                 __half* __restrict__ L, int n4) {
  int i = blockIdx.x * 256 + threadIdx.x;
  if (i >= n4) return;
  float4 v = ((const float4*)s)[i];
  __half h0,l0,h1,l1,h2,l2,h3,l3;
  f16_split(v.x,h0,l0); f16_split(v.y,h1,l1); f16_split(v.z,h2,l2); f16_split(v.w,h3,l3);
  __half2* Hp = (__half2*)(H + (size_t)i*4);
  __half2* Lp = (__half2*)(L + (size_t)i*4);
  Hp[0] = __halves2half2(h0,h1); Hp[1] = __halves2half2(h2,h3);
  Lp[0] = __halves2half2(l0,l1); Lp[1] = __halves2half2(l2,l3);
}

// ---------------------------------------------------------------------------
// Weight transpose+split: g_Wth/l[(p*16+h)*64 + d][e] = W_p[h][e][d]
// ---------------------------------------------------------------------------
__global__ __launch_bounds__(256) void transpose_w(
    const float* __restrict__ Wq, const float* __restrict__ Wk,
    const float* __restrict__ Wv) {
  __shared__ float t[32][33];
  const int bz = blockIdx.z;             // p*16+h
  const int p = bz >> 4;
  const float* W = (p == 0 ? Wq : p == 1 ? Wk : Wv) + (size_t)(bz & 15) * EE * DH;
  const int e0 = blockIdx.x * 32;
  const int d0 = blockIdx.y * 32;
  const int tx = threadIdx.x, ty = threadIdx.y;
  #pragma unroll
  for (int i = ty; i < 32; i += 8)
    t[i][tx] = W[(size_t)(e0 + i) * DH + d0 + tx];
  __syncthreads();
  #pragma unroll
  for (int i = ty; i < 32; i += 8) {
    size_t idx = (size_t)(bz * DH + d0 + i) * EE + e0 + tx;
    store_split(g_Wth, g_Wtl, idx, t[tx][i]);
  }
}

// ---------------------------------------------------------------------------
// fp16 3-pass GEMM. BM=128 BN=128 BK=32, 256 thr, cp.async double buffer.
// C[m][n] = sum_k A[m][k]*B[n][k] (both K-major halves).
// MODE 0: A=x halves, B=Wt halves -> split-write Q/K (t-major) + Vt (d-major)
// MODE 1: A=attn-out halves, B=Wo halves -> fp32 out + bias
// ---------------------------------------------------------------------------
#define G_TILE_H 5120                 // halves per tile (128*40)
#define G_STAGE_B (4 * G_TILE_H * 2)  // 40960 bytes
#define GEMM_SMEM (2 * G_STAGE_B)

template<int MODE>
__global__ __launch_bounds__(256, 2) void gemm_f16(
    const __half* __restrict__ pAh, const __half* __restrict__ pAl,
    const __half* __restrict__ pBh, const __half* __restrict__ pBl,
    const float* __restrict__ bias, float* __restrict__ outp) {
  extern __shared__ __align__(16) char gsm[];
  const int tid = threadIdx.x;
  const int lane = tid & 31, q = lane & 3, g = lane >> 2;
  const int wid = tid >> 5, wm = wid >> 2, wn = wid & 3;
  const int n0 = blockIdx.x * 128;
  const size_t m0 = (size_t)blockIdx.y * 128;
  const uint32_t s0 = smem_u32(gsm);

  float C[4][4][4];
  #pragma unroll
  for (int a = 0; a < 4; a++)
    #pragma unroll
    for (int b = 0; b < 4; b++)
      #pragma unroll
      for (int c = 0; c < 4; c++) C[a][b][c] = 0.f;

  auto issue = [&](int stage, int k0) {
    const uint32_t sb = s0 + stage * G_STAGE_B;
    #pragma unroll
    for (int t = 0; t < 8; t++) {
      int c = tid + t * 256;
      int arr = c >> 9, rem = c & 511;
      int row = rem >> 2, seg = rem & 3;
      const __half* src;
      if (arr == 0)      src = pAh + (m0 + row) * EE + k0 + seg * 8;
      else if (arr == 1) src = pAl + (m0 + row) * EE + k0 + seg * 8;
      else if (arr == 2) src = pBh + (size_t)(n0 + row) * EE + k0 + seg * 8;
      else               src = pBl + (size_t)(n0 + row) * EE + k0 + seg * 8;
      cp16(sb + (uint32_t)(arr * G_TILE_H + row * 40 + seg * 8) * 2, src);
    }
    cp_commit();
  };

  issue(0, 0);
  for (int i = 0; i < EE / 32; i++) {
    if (i + 1 < EE / 32) { issue((i + 1) & 1, (i + 1) * 32); cp_wait<1>(); }
    else cp_wait<0>();
    __syncthreads();
    const uint32_t sb = s0 + (i & 1) * G_STAGE_B;
    const uint32_t tAh = sb, tAl = sb + G_TILE_H*2, tBh = sb + 2*G_TILE_H*2, tBl = sb + 3*G_TILE_H*2;
    #pragma unroll
    for (int kc = 0; kc < 2; kc++) {
      uint32_t ah[4][4], al[4][4];
      #pragma unroll
      for (int mt = 0; mt < 4; mt++) {
        const int r = wm * 64 + mt * 16 + g;
        const uint32_t o0 = (uint32_t)((r * 40 + kc * 16 + 2 * q) * 2);
        const uint32_t o1 = o0 + 8 * 40 * 2;
        ah[mt][0] = lds32(tAh + o0); ah[mt][1] = lds32(tAh + o1);
        ah[mt][2] = lds32(tAh + o0 + 16); ah[mt][3] = lds32(tAh + o1 + 16);
        al[mt][0] = lds32(tAl + o0); al[mt][1] = lds32(tAl + o1);
        al[mt][2] = lds32(tAl + o0 + 16); al[mt][3] = lds32(tAl + o1 + 16);
      }
      #pragma unroll
      for (int nt = 0; nt < 4; nt++) {
        const int n = wn * 32 + nt * 8 + g;
        const uint32_t o = (uint32_t)((n * 40 + kc * 16 + 2 * q) * 2);
        const uint32_t bh0 = lds32(tBh + o), bh1 = lds32(tBh + o + 16);
        const uint32_t bl0 = lds32(tBl + o), bl1 = lds32(tBl + o + 16);
        #pragma unroll
        for (int mt = 0; mt < 4; mt++) {
          mma_f16(C[mt][nt], ah[mt][0], ah[mt][1], ah[mt][2], ah[mt][3], bh0, bh1);
          mma_f16(C[mt][nt], ah[mt][0], ah[mt][1], ah[mt][2], ah[mt][3], bl0, bl1);
          mma_f16(C[mt][nt], al[mt][0], al[mt][1], al[mt][2], al[mt][3], bh0, bh1);
        }
      }
    }
    __syncthreads();
  }

  // epilogue
  #pragma unroll
  for (int mt = 0; mt < 4; mt++) {
    #pragma unroll
    for (int nt = 0; nt < 4; nt++) {
      #pragma unroll
      for (int e = 0; e < 4; e++) {
        const int r = (int)m0 + wm * 64 + mt * 16 + g + (e >= 2 ? 8 : 0);
        const int c = n0 + wn * 32 + nt * 8 + 2 * q + (e & 1);
        const float v = C[mt][nt][e];
        if (MODE == 0) {
          const int p = c >> 10, rl = c & 1023, hh = rl >> 6, d = rl & 63;
          const int bhi = (r >> 11) * HH + hh, t = r & (TT - 1);
          if (p == 2) {
            store_split(g_Vth, g_Vtl, ((size_t)bhi * DH + d) * TT + t, v);
          } else {
            size_t idx = ((size_t)bhi * TT + t) * DH + d;
            if (p == 0) store_split(g_Qh, g_Ql, idx, v);
            else        store_split(g_Kh, g_Kl, idx, v);
          }
        } else {
          outp[(size_t)r * EE + c] = v + bias[c];
        }
      }
    }
  }
}

// ---------------------------------------------------------------------------
// fp16 3-pass flash attention. CTA: 128 queries of one (b,h); 8 warps,
// warp = 16 rows x full key width. 64-key blocks, cp.async double buffer.
// ---------------------------------------------------------------------------
#define AT_Q_H   9216       // 128*72
#define AT_T_H   4608       // 64*72
#define AT_KV_H  (4 * AT_T_H)
#define ATT_SMEM ((2 * AT_Q_H + 2 * AT_KV_H) * 2)   // 110592 bytes

__global__ __launch_bounds__(256, 2) void attn_f16() {
  extern __shared__ __align__(16) char asm_[];
  const int tid = threadIdx.x;
  const int lane = tid & 31, q = lane & 3, g = lane >> 2;
  const int wid = tid >> 5;
  const int i0 = ((int)gridDim.x - 1 - (int)blockIdx.x) * 128;  // heavy CTAs first
  const int bh = blockIdx.y;
  const uint32_t s0 = smem_u32(asm_);
  const uint32_t pQh = s0, pQl = s0 + AT_Q_H * 2;
  const uint32_t kvBase = s0 + 2 * AT_Q_H * 2;

  // ---- issue Q (once) ----
  #pragma unroll
  for (int t = 0; t < 8; t++) {
    int c = tid + t * 256;
    int arr = c >> 10, rem = c & 1023, row = rem >> 3, seg = rem & 7;
    const __half* src = (arr ? g_Ql : g_Qh) + ((size_t)bh * TT + i0 + row) * DH + seg * 8;
    cp16((arr ? pQl : pQh) + (uint32_t)(row * 72 + seg * 8) * 2, src);
  }
  // ---- KV issue helper ----
  auto issue_kv = [&](int stage, int j0) {
    const uint32_t kb = kvBase + stage * AT_KV_H * 2;
    #pragma unroll
    for (int t = 0; t < 8; t++) {
      int c = tid + t * 256;
      int arr = c >> 9, rem = c & 511, row = rem >> 3, seg = rem & 7;
      const __half* src;
      if (arr == 0)      src = g_Kh  + ((size_t)bh * TT + j0 + row) * DH + seg * 8;
      else if (arr == 1) src = g_Kl  + ((size_t)bh * TT + j0 + row) * DH + seg * 8;
      else if (arr == 2) src = g_Vth + ((size_t)bh * DH + row) * TT + j0 + seg * 8;
      else               src = g_Vtl + ((size_t)bh * DH + row) * TT + j0 + seg * 8;
      cp16(kb + (uint32_t)(arr * AT_T_H + row * 72 + seg * 8) * 2, src);
    }
    cp_commit();
  };

  const int nb = i0 / 64 + 2;
  issue_kv(0, 0);   // group 0 = Q + KV block 0

  float O[8][4];
  #pragma unroll
  for (int a = 0; a < 8; a++)
    #pragma unroll
    for (int e = 0; e < 4; e++) O[a][e] = 0.f;
  float m0r = -1e30f, m1r = -1e30f, l0r = 0.f, l1r = 0.f;
  const int row0g = i0 + wid * 16 + g;   // sequence-local (used for causal mask)
  const int row1g = row0g + 8;

  for (int jb = 0; jb < nb; jb++) {
    if (jb + 1 < nb) { issue_kv((jb + 1) & 1, (jb + 1) * 64); cp_wait<1>(); }
    else cp_wait<0>();
    __syncthreads();
    const uint32_t kb = kvBase + (jb & 1) * AT_KV_H * 2;
    const uint32_t tKh = kb, tKl = kb + AT_T_H*2, tVh = kb + 2*AT_T_H*2, tVl = kb + 3*AT_T_H*2;

    // S = Q K^T (3-pass)
    float S[8][4];
    #pragma unroll
    for (int a = 0; a < 8; a++)
      #pragma unroll
      for (int e = 0; e < 4; e++) S[a][e] = 0.f;
    #pragma unroll
    for (int kc = 0; kc < 4; kc++) {
      const uint32_t oa0 = (uint32_t)(((wid * 16 + g) * 72 + kc * 16 + 2 * q) * 2);
      const uint32_t oa1 = oa0 + 8 * 72 * 2;
      const uint32_t qh0 = lds32(pQh + oa0), qh1 = lds32(pQh + oa1);
      const uint32_t qh2 = lds32(pQh + oa0 + 16), qh3 = lds32(pQh + oa1 + 16);
      const uint32_t ql0 = lds32(pQl + oa0), ql1 = lds32(pQl + oa1);
      const uint32_t ql2 = lds32(pQl + oa0 + 16), ql3 = lds32(pQl + oa1 + 16);
      #pragma unroll
      for (int nt = 0; nt < 8; nt++) {
        const uint32_t ob = (uint32_t)(((nt * 8 + g) * 72 + kc * 16 + 2 * q) * 2);
        const uint32_t kh0 = lds32(tKh + ob), kh1 = lds32(tKh + ob + 16);
        const uint32_t kl0 = lds32(tKl + ob), kl1 = lds32(tKl + ob + 16);
        mma_f16(S[nt], qh0, qh1, qh2, qh3, kh0, kh1);
        mma_f16(S[nt], qh0, qh1, qh2, qh3, kl0, kl1);
        mma_f16(S[nt], ql0, ql1, ql2, ql3, kh0, kh1);
      }
    }

    // scale + causal mask
    const int j0 = jb * 64;
    #pragma unroll
    for (int nt = 0; nt < 8; nt++)
      #pragma unroll
      for (int e = 0; e < 4; e++) S[nt][e] *= 0.125f;
    if (j0 >= i0) {
      #pragma unroll
      for (int nt = 0; nt < 8; nt++) {
        const int cb = j0 + nt * 8 + 2 * q;
        if (cb     > row0g) S[nt][0] = -1e30f;
        if (cb + 1 > row0g) S[nt][1] = -1e30f;
        if (cb     > row1g) S[nt][2] = -1e30f;
        if (cb + 1 > row1g) S[nt][3] = -1e30f;
      }
    }

    // online softmax (2 rows per thread)
    float mx0 = -1e30f, mx1 = -1e30f;
    #pragma unroll
    for (int nt = 0; nt < 8; nt++) {
      mx0 = fmaxf(mx0, fmaxf(S[nt][0], S[nt][1]));
      mx1 = fmaxf(mx1, fmaxf(S[nt][2], S[nt][3]));
    }
    mx0 = fmaxf(mx0, __shfl_xor_sync(0xffffffffu, mx0, 1));
    mx0 = fmaxf(mx0, __shfl_xor_sync(0xffffffffu, mx0, 2));
    mx1 = fmaxf(mx1, __shfl_xor_sync(0xffffffffu, mx1, 1));
    mx1 = fmaxf(mx1, __shfl_xor_sync(0xffffffffu, mx1, 2));
    const float mn0 = fmaxf(m0r, mx0), mn1 = fmaxf(m1r, mx1);
    const float al0 = __expf(m0r - mn0), al1 = __expf(m1r - mn1);
    m0r = mn0; m1r = mn1;
    float ls0 = 0.f, ls1 = 0.f;
    #pragma unroll
    for (int nt = 0; nt < 8; nt++) {
      S[nt][0] = __expf(S[nt][0] - mn0); ls0 += S[nt][0];
      S[nt][1] = __expf(S[nt][1] - mn0); ls0 += S[nt][1];
      S[nt][2] = __expf(S[nt][2] - mn1); ls1 += S[nt][2];
      S[nt][3] = __expf(S[nt][3] - mn1); ls1 += S[nt][3];
    }
    ls0 += __shfl_xor_sync(0xffffffffu, ls0, 1);
    ls0 += __shfl_xor_sync(0xffffffffu, ls0, 2);
    ls1 += __shfl_xor_sync(0xffffffffu, ls1, 1);
    ls1 += __shfl_xor_sync(0xffffffffu, ls1, 2);
    l0r = l0r * al0 + ls0;
    l1r = l1r * al1 + ls1;
    #pragma unroll
    for (int nt = 0; nt < 8; nt++) {
      O[nt][0] *= al0; O[nt][1] *= al0;
      O[nt][2] *= al1; O[nt][3] *= al1;
    }

    // O += P V (3-pass); P fragments come straight from S registers
    #pragma unroll
    for (int kc = 0; kc < 4; kc++) {
      uint32_t a0h, a0l, a1h, a1l, a2h, a2l, a3h, a3l;
      split2(S[2*kc][0],   S[2*kc][1],   a0h, a0l);
      split2(S[2*kc][2],   S[2*kc][3],   a1h, a1l);
      split2(S[2*kc+1][0], S[2*kc+1][1], a2h, a2l);
      split2(S[2*kc+1][2], S[2*kc+1][3], a3h, a3l);
      #pragma unroll
      for (int nd = 0; nd < 8; nd++) {
        const uint32_t ov = (uint32_t)(((nd * 8 + g) * 72 + kc * 16 + 2 * q) * 2);
        const uint32_t vh0 = lds32(tVh + ov), vh1 = lds32(tVh + ov + 16);
        const uint32_t vl0 = lds32(tVl + ov), vl1 = lds32(tVl + ov + 16);
        mma_f16(O[nd], a0h, a1h, a2h, a3h, vh0, vh1);
        mma_f16(O[nd], a0h, a1h, a2h, a3h, vl0, vl1);
        mma_f16(O[nd], a0l, a1l, a2l, a3l, vh0, vh1);
      }
    }
    __syncthreads();
  }

  // epilogue: normalize, split-write to g_Ah/g_Al at [b*TT + t][h*64 + d]
  // (R4 bug fix: include the batch offset in the output row)
  const float inv0 = 1.f / l0r, inv1 = 1.f / l1r;
  const int colb = (bh & 15) * DH;
  const size_t orow0 = (size_t)(bh >> 4) * TT + row0g;
  const size_t orow1 = orow0 + 8;
  #pragma unroll
  for (int nd = 0; nd < 8; nd++) {
    const int d0 = nd * 8 + 2 * q;
    const size_t i00 = orow0 * EE + colb + d0;
    const size_t i10 = orow1 * EE + colb + d0;
    store_split(g_Ah, g_Al, i00,     O[nd][0] * inv0);
    store_split(g_Ah, g_Al, i00 + 1, O[nd][1] * inv0);
    store_split(g_Ah, g_Al, i10,     O[nd][2] * inv1);
    store_split(g_Ah, g_Al, i10 + 1, O[nd][3] * inv1);
  }
}

// ---------------------------------------------------------------------------
extern "C" void kernel_launch(void* const* d_in, const int* in_sizes, int n_in,
                              void* d_out, int out_size) {
  const float* x  = (const float*)d_in[0];
  const float* Wq = (const float*)d_in[1];
  const float* Wk = (const float*)d_in[2];
  const float* Wv = (const float*)d_in[3];
  const float* Wo = (const float*)d_in[4];
  const float* wb = (const float*)d_in[5];
  float* out = (float*)d_out;

  __half *xh, *xl, *wth, *wtl, *woh, *wol, *ah, *al;
  cudaGetSymbolAddress((void**)&xh, g_xh);   cudaGetSymbolAddress((void**)&xl, g_xl);
  cudaGetSymbolAddress((void**)&wth, g_Wth); cudaGetSymbolAddress((void**)&wtl, g_Wtl);
  cudaGetSymbolAddress((void**)&woh, g_Woh); cudaGetSymbolAddress((void**)&wol, g_Wol);
  cudaGetSymbolAddress((void**)&ah, g_Ah);   cudaGetSymbolAddress((void**)&al, g_Al);

  cudaFuncSetAttribute(gemm_f16<0>, cudaFuncAttributeMaxDynamicSharedMemorySize, GEMM_SMEM);
  cudaFuncSetAttribute(gemm_f16<1>, cudaFuncAttributeMaxDynamicSharedMemorySize, GEMM_SMEM);
  cudaFuncSetAttribute(attn_f16, cudaFuncAttributeMaxDynamicSharedMemorySize, ATT_SMEM);

  split_f32<<<(MTOT*EE/4 + 255)/256, 256>>>(x, xh, xl, MTOT*EE/4);
  split_f32<<<(EE*EE/4 + 255)/256, 256>>>(Wo, woh, wol, EE*EE/4);
  transpose_w<<<dim3(EE/32, DH/32, 48), dim3(32, 8)>>>(Wq, Wk, Wv);

  gemm_f16<0><<<dim3(3*EE/128, MTOT/128), 256, GEMM_SMEM>>>(xh, xl, wth, wtl, nullptr, nullptr);

  attn_f16<<<dim3(TT/128, BHN), 256, ATT_SMEM>>>();

  gemm_f16<1><<<dim3(EE/128, MTOT/128), 256, GEMM_SMEM>>>(ah, al, woh, wol, wb, out);
}

// round 6
// speedup vs baseline: 2.7165x; 1.1132x over previous
#include <cuda_runtime.h>
#include <cuda_fp16.h>
#include <cstdint>

#define BB 2
#define TT 2048
#define EE 1024
#define HH 16
#define DH 64
#define MTOT (BB*TT)   // 4096
#define BHN (BB*HH)    // 32

// ---------------------------------------------------------------------------
// Global scratch (allocation-free rule): fp16 hi/lo split arrays
// ---------------------------------------------------------------------------
__device__ __align__(128) __half g_xh[(size_t)MTOT*EE];
__device__ __align__(128) __half g_xl[(size_t)MTOT*EE];
__device__ __align__(128) __half g_Wth[(size_t)3*EE*EE];   // [3072][1024]
__device__ __align__(128) __half g_Wtl[(size_t)3*EE*EE];
__device__ __align__(128) __half g_Qh[(size_t)BHN*TT*DH];  // [bh][t][d]
__device__ __align__(128) __half g_Ql[(size_t)BHN*TT*DH];
__device__ __align__(128) __half g_Kh[(size_t)BHN*TT*DH];  // [bh][t][d]
__device__ __align__(128) __half g_Kl[(size_t)BHN*TT*DH];
__device__ __align__(128) __half g_Vth[(size_t)BHN*TT*DH]; // [bh][d][t]
__device__ __align__(128) __half g_Vtl[(size_t)BHN*TT*DH];
__device__ __align__(128) __half g_Ah[(size_t)MTOT*EE];    // attn out
__device__ __align__(128) __half g_Al[(size_t)MTOT*EE];
__device__ __align__(128) __half g_Woh[(size_t)EE*EE];     // [out][in]
__device__ __align__(128) __half g_Wol[(size_t)EE*EE];

// ---------------------------------------------------------------------------
// Helpers
// ---------------------------------------------------------------------------
__device__ __forceinline__ uint32_t smem_u32(const void* p) {
  uint32_t a;
  asm("{ .reg .u64 t; cvta.to.shared.u64 t, %1; cvt.u32.u64 %0, t; }" : "=r"(a) : "l"(p));
  return a;
}
__device__ __forceinline__ void ldsm4(uint32_t addr, uint32_t r[4]) {
  asm volatile("ldmatrix.sync.aligned.m8n8.x4.shared.b16 {%0,%1,%2,%3}, [%4];"
               : "=r"(r[0]), "=r"(r[1]), "=r"(r[2]), "=r"(r[3]) : "r"(addr));
}
__device__ __forceinline__ void cp16(uint32_t dst, const void* src) {
  asm volatile("cp.async.ca.shared.global [%0], [%1], 16;" :: "r"(dst), "l"(src) : "memory");
}
__device__ __forceinline__ void cp_commit() {
  asm volatile("cp.async.commit_group;" ::: "memory");
}
template<int N> __device__ __forceinline__ void cp_wait() {
  asm volatile("cp.async.wait_group %0;" :: "n"(N) : "memory");
}
__device__ __forceinline__ void f16_split(float x, __half& h, __half& l) {
  h = __float2half_rn(x);
  l = __float2half_rn(x - __half2float(h));
}
__device__ __forceinline__ void store_split(__half* H, __half* L, size_t idx, float v) {
  __half h, l; f16_split(v, h, l);
  H[idx] = h; L[idx] = l;
}
__device__ __forceinline__ void split2(float a, float b, uint32_t& hi, uint32_t& lo) {
  __half ha, la, hb, lb;
  f16_split(a, ha, la); f16_split(b, hb, lb);
  __half2 H = __halves2half2(ha, hb), L = __halves2half2(la, lb);
  hi = *(uint32_t*)&H; lo = *(uint32_t*)&L;
}
__device__ __forceinline__ void mma_f16(float c[4], uint32_t a0, uint32_t a1,
                                        uint32_t a2, uint32_t a3,
                                        uint32_t b0, uint32_t b1) {
  asm volatile(
    "mma.sync.aligned.m16n8k16.row.col.f32.f16.f16.f32 "
    "{%0,%1,%2,%3},{%4,%5,%6,%7},{%8,%9},{%0,%1,%2,%3};"
    : "+f"(c[0]), "+f"(c[1]), "+f"(c[2]), "+f"(c[3])
    : "r"(a0), "r"(a1), "r"(a2), "r"(a3), "r"(b0), "r"(b1));
}

// ---------------------------------------------------------------------------
// Pre-split: fp32 -> (hi, lo) halves.
// ---------------------------------------------------------------------------
__global__ __launch_bounds__(256) void split_f32(const float* __restrict__ s,
                                                 __half* __restrict__ H,
                                                 __half* __restrict__ L, int n4) {
  int i = blockIdx.x * 256 + threadIdx.x;
  if (i >= n4) return;
  float4 v = ((const float4*)s)[i];
  __half h0,l0,h1,l1,h2,l2,h3,l3;
  f16_split(v.x,h0,l0); f16_split(v.y,h1,l1); f16_split(v.z,h2,l2); f16_split(v.w,h3,l3);
  __half2* Hp = (__half2*)(H + (size_t)i*4);
  __half2* Lp = (__half2*)(L + (size_t)i*4);
  Hp[0] = __halves2half2(h0,h1); Hp[1] = __halves2half2(h2,h3);
  Lp[0] = __halves2half2(l0,l1); Lp[1] = __halves2half2(l2,l3);
}

// ---------------------------------------------------------------------------
// Weight transpose+split: g_Wth/l[(p*16+h)*64 + d][e] = W_p[h][e][d]
// ---------------------------------------------------------------------------
__global__ __launch_bounds__(256) void transpose_w(
    const float* __restrict__ Wq, const float* __restrict__ Wk,
    const float* __restrict__ Wv) {
  __shared__ float t[32][33];
  const int bz = blockIdx.z;             // p*16+h
  const int p = bz >> 4;
  const float* W = (p == 0 ? Wq : p == 1 ? Wk : Wv) + (size_t)(bz & 15) * EE * DH;
  const int e0 = blockIdx.x * 32;
  const int d0 = blockIdx.y * 32;
  const int tx = threadIdx.x, ty = threadIdx.y;
  #pragma unroll
  for (int i = ty; i < 32; i += 8)
    t[i][tx] = W[(size_t)(e0 + i) * DH + d0 + tx];
  __syncthreads();
  #pragma unroll
  for (int i = ty; i < 32; i += 8) {
    size_t idx = (size_t)(bz * DH + d0 + i) * EE + e0 + tx;
    store_split(g_Wth, g_Wtl, idx, t[tx][i]);
  }
}

// ---------------------------------------------------------------------------
// fp16 3-pass GEMM. BM=128 BN=128 BK=32, 256 thr, cp.async double buffer,
// ldmatrix fragment loads.
// ---------------------------------------------------------------------------
#define G_TILE_H 5120                 // halves per tile (128*40)
#define G_STAGE_B (4 * G_TILE_H * 2)  // 40960 bytes
#define GEMM_SMEM (2 * G_STAGE_B)

template<int MODE>
__global__ __launch_bounds__(256, 2) void gemm_f16(
    const __half* __restrict__ pAh, const __half* __restrict__ pAl,
    const __half* __restrict__ pBh, const __half* __restrict__ pBl,
    const float* __restrict__ bias, float* __restrict__ outp) {
  extern __shared__ __align__(16) char gsm[];
  const int tid = threadIdx.x;
  const int lane = tid & 31, q = lane & 3, g = lane >> 2;
  const int wid = tid >> 5, wm = wid >> 2, wn = wid & 3;
  const int n0 = blockIdx.x * 128;
  const size_t m0 = (size_t)blockIdx.y * 128;
  const uint32_t s0 = smem_u32(gsm);

  // ldmatrix lane-address components
  const int a_row = lane & 15;                       // + mt*16 + wm*64
  const int a_col = (lane >> 4) << 3;                // + kc*16
  const int b_row = (lane & 7) + ((lane >> 4) << 3); // + np*16 + wn*32
  const int b_col = ((lane >> 3) & 1) << 3;          // + kc*16

  float C[4][4][4];
  #pragma unroll
  for (int a = 0; a < 4; a++)
    #pragma unroll
    for (int b = 0; b < 4; b++)
      #pragma unroll
      for (int c = 0; c < 4; c++) C[a][b][c] = 0.f;

  auto issue = [&](int stage, int k0) {
    const uint32_t sb = s0 + stage * G_STAGE_B;
    #pragma unroll
    for (int t = 0; t < 8; t++) {
      int c = tid + t * 256;
      int arr = c >> 9, rem = c & 511;
      int row = rem >> 2, seg = rem & 3;
      const __half* src;
      if (arr == 0)      src = pAh + (m0 + row) * EE + k0 + seg * 8;
      else if (arr == 1) src = pAl + (m0 + row) * EE + k0 + seg * 8;
      else if (arr == 2) src = pBh + (size_t)(n0 + row) * EE + k0 + seg * 8;
      else               src = pBl + (size_t)(n0 + row) * EE + k0 + seg * 8;
      cp16(sb + (uint32_t)(arr * G_TILE_H + row * 40 + seg * 8) * 2, src);
    }
    cp_commit();
  };

  issue(0, 0);
  for (int i = 0; i < EE / 32; i++) {
    if (i + 1 < EE / 32) { issue((i + 1) & 1, (i + 1) * 32); cp_wait<1>(); }
    else cp_wait<0>();
    __syncthreads();
    const uint32_t sb = s0 + (i & 1) * G_STAGE_B;
    const uint32_t tAh = sb, tAl = sb + G_TILE_H*2, tBh = sb + 2*G_TILE_H*2, tBl = sb + 3*G_TILE_H*2;
    #pragma unroll
    for (int kc = 0; kc < 2; kc++) {
      const int kc16 = kc * 16;
      uint32_t ah[4][4], al[4][4];
      #pragma unroll
      for (int mt = 0; mt < 4; mt++) {
        const uint32_t off = (uint32_t)(((wm * 64 + mt * 16 + a_row) * 40 + kc16 + a_col) * 2);
        ldsm4(tAh + off, ah[mt]);
        ldsm4(tAl + off, al[mt]);
      }
      uint32_t bhf[2][4], blf[2][4];
      #pragma unroll
      for (int np = 0; np < 2; np++) {
        const uint32_t off = (uint32_t)(((wn * 32 + np * 16 + b_row) * 40 + kc16 + b_col) * 2);
        ldsm4(tBh + off, bhf[np]);
        ldsm4(tBl + off, blf[np]);
      }
      #pragma unroll
      for (int np = 0; np < 2; np++) {
        #pragma unroll
        for (int j = 0; j < 2; j++) {
          const int nt = np * 2 + j;
          const uint32_t b0h = bhf[np][2*j], b1h = bhf[np][2*j+1];
          const uint32_t b0l = blf[np][2*j], b1l = blf[np][2*j+1];
          #pragma unroll
          for (int mt = 0; mt < 4; mt++) {
            mma_f16(C[mt][nt], ah[mt][0], ah[mt][1], ah[mt][2], ah[mt][3], b0h, b1h);
            mma_f16(C[mt][nt], ah[mt][0], ah[mt][1], ah[mt][2], ah[mt][3], b0l, b1l);
            mma_f16(C[mt][nt], al[mt][0], al[mt][1], al[mt][2], al[mt][3], b0h, b1h);
          }
        }
      }
    }
    __syncthreads();
  }

  // epilogue
  #pragma unroll
  for (int mt = 0; mt < 4; mt++) {
    #pragma unroll
    for (int nt = 0; nt < 4; nt++) {
      #pragma unroll
      for (int e = 0; e < 4; e++) {
        const int r = (int)m0 + wm * 64 + mt * 16 + g + (e >= 2 ? 8 : 0);
        const int c = n0 + wn * 32 + nt * 8 + 2 * q + (e & 1);
        const float v = C[mt][nt][e];
        if (MODE == 0) {
          const int p = c >> 10, rl = c & 1023, hh = rl >> 6, d = rl & 63;
          const int bhi = (r >> 11) * HH + hh, t = r & (TT - 1);
          if (p == 2) {
            store_split(g_Vth, g_Vtl, ((size_t)bhi * DH + d) * TT + t, v);
          } else {
            size_t idx = ((size_t)bhi * TT + t) * DH + d;
            if (p == 0) store_split(g_Qh, g_Ql, idx, v);
            else        store_split(g_Kh, g_Kl, idx, v);
          }
        } else {
          outp[(size_t)r * EE + c] = v + bias[c];
        }
      }
    }
  }
}

// ---------------------------------------------------------------------------
// fp16 3-pass flash attention with ldmatrix fragment loads.
// ---------------------------------------------------------------------------
#define AT_Q_H   9216       // 128*72
#define AT_T_H   4608       // 64*72
#define AT_KV_H  (4 * AT_T_H)
#define ATT_SMEM ((2 * AT_Q_H + 2 * AT_KV_H) * 2)   // 110592 bytes

__global__ __launch_bounds__(256, 2) void attn_f16() {
  extern __shared__ __align__(16) char asm_[];
  const int tid = threadIdx.x;
  const int lane = tid & 31, q = lane & 3, g = lane >> 2;
  const int wid = tid >> 5;
  const int i0 = ((int)gridDim.x - 1 - (int)blockIdx.x) * 128;  // heavy CTAs first
  const int bh = blockIdx.y;
  const uint32_t s0 = smem_u32(asm_);
  const uint32_t pQh = s0, pQl = s0 + AT_Q_H * 2;
  const uint32_t kvBase = s0 + 2 * AT_Q_H * 2;

  const int a_row = lane & 15;
  const int a_col = (lane >> 4) << 3;
  const int b_row = (lane & 7) + ((lane >> 4) << 3);
  const int b_col = ((lane >> 3) & 1) << 3;

  // ---- issue Q (once) ----
  #pragma unroll
  for (int t = 0; t < 8; t++) {
    int c = tid + t * 256;
    int arr = c >> 10, rem = c & 1023, row = rem >> 3, seg = rem & 7;
    const __half* src = (arr ? g_Ql : g_Qh) + ((size_t)bh * TT + i0 + row) * DH + seg * 8;
    cp16((arr ? pQl : pQh) + (uint32_t)(row * 72 + seg * 8) * 2, src);
  }
  auto issue_kv = [&](int stage, int j0) {
    const uint32_t kb = kvBase + stage * AT_KV_H * 2;
    #pragma unroll
    for (int t = 0; t < 8; t++) {
      int c = tid + t * 256;
      int arr = c >> 9, rem = c & 511, row = rem >> 3, seg = rem & 7;
      const __half* src;
      if (arr == 0)      src = g_Kh  + ((size_t)bh * TT + j0 + row) * DH + seg * 8;
      else if (arr == 1) src = g_Kl  + ((size_t)bh * TT + j0 + row) * DH + seg * 8;
      else if (arr == 2) src = g_Vth + ((size_t)bh * DH + row) * TT + j0 + seg * 8;
      else               src = g_Vtl + ((size_t)bh * DH + row) * TT + j0 + seg * 8;
      cp16(kb + (uint32_t)(arr * AT_T_H + row * 72 + seg * 8) * 2, src);
    }
    cp_commit();
  };

  const int nb = i0 / 64 + 2;
  issue_kv(0, 0);

  float O[8][4];
  #pragma unroll
  for (int a = 0; a < 8; a++)
    #pragma unroll
    for (int e = 0; e < 4; e++) O[a][e] = 0.f;
  float m0r = -1e30f, m1r = -1e30f, l0r = 0.f, l1r = 0.f;
  const int row0g = i0 + wid * 16 + g;   // sequence-local (causal mask)
  const int row1g = row0g + 8;

  for (int jb = 0; jb < nb; jb++) {
    if (jb + 1 < nb) { issue_kv((jb + 1) & 1, (jb + 1) * 64); cp_wait<1>(); }
    else cp_wait<0>();
    __syncthreads();
    const uint32_t kb = kvBase + (jb & 1) * AT_KV_H * 2;
    const uint32_t tKh = kb, tKl = kb + AT_T_H*2, tVh = kb + 2*AT_T_H*2, tVl = kb + 3*AT_T_H*2;

    // S = Q K^T (3-pass)
    float S[8][4];
    #pragma unroll
    for (int a = 0; a < 8; a++)
      #pragma unroll
      for (int e = 0; e < 4; e++) S[a][e] = 0.f;
    #pragma unroll
    for (int kc = 0; kc < 4; kc++) {
      const int kc16 = kc * 16;
      uint32_t qh[4], ql[4];
      const uint32_t qoff = (uint32_t)(((wid * 16 + a_row) * 72 + kc16 + a_col) * 2);
      ldsm4(pQh + qoff, qh);
      ldsm4(pQl + qoff, ql);
      #pragma unroll
      for (int np = 0; np < 4; np++) {
        uint32_t kh[4], kl[4];
        const uint32_t koff = (uint32_t)(((np * 16 + b_row) * 72 + kc16 + b_col) * 2);
        ldsm4(tKh + koff, kh);
        ldsm4(tKl + koff, kl);
        #pragma unroll
        for (int j = 0; j < 2; j++) {
          const int nt = np * 2 + j;
          mma_f16(S[nt], qh[0], qh[1], qh[2], qh[3], kh[2*j], kh[2*j+1]);
          mma_f16(S[nt], qh[0], qh[1], qh[2], qh[3], kl[2*j], kl[2*j+1]);
          mma_f16(S[nt], ql[0], ql[1], ql[2], ql[3], kh[2*j], kh[2*j+1]);
        }
      }
    }

    // scale + causal mask
    const int j0 = jb * 64;
    #pragma unroll
    for (int nt = 0; nt < 8; nt++)
      #pragma unroll
      for (int e = 0; e < 4; e++) S[nt][e] *= 0.125f;
    if (j0 >= i0) {
      #pragma unroll
      for (int nt = 0; nt < 8; nt++) {
        const int cb = j0 + nt * 8 + 2 * q;
        if (cb     > row0g) S[nt][0] = -1e30f;
        if (cb + 1 > row0g) S[nt][1] = -1e30f;
        if (cb     > row1g) S[nt][2] = -1e30f;
        if (cb + 1 > row1g) S[nt][3] = -1e30f;
      }
    }

    // online softmax (2 rows per thread)
    float mx0 = -1e30f, mx1 = -1e30f;
    #pragma unroll
    for (int nt = 0; nt < 8; nt++) {
      mx0 = fmaxf(mx0, fmaxf(S[nt][0], S[nt][1]));
      mx1 = fmaxf(mx1, fmaxf(S[nt][2], S[nt][3]));
    }
    mx0 = fmaxf(mx0, __shfl_xor_sync(0xffffffffu, mx0, 1));
    mx0 = fmaxf(mx0, __shfl_xor_sync(0xffffffffu, mx0, 2));
    mx1 = fmaxf(mx1, __shfl_xor_sync(0xffffffffu, mx1, 1));
    mx1 = fmaxf(mx1, __shfl_xor_sync(0xffffffffu, mx1, 2));
    const float mn0 = fmaxf(m0r, mx0), mn1 = fmaxf(m1r, mx1);
    const float al0 = __expf(m0r - mn0), al1 = __expf(m1r - mn1);
    m0r = mn0; m1r = mn1;
    float ls0 = 0.f, ls1 = 0.f;
    #pragma unroll
    for (int nt = 0; nt < 8; nt++) {
      S[nt][0] = __expf(S[nt][0] - mn0); ls0 += S[nt][0];
      S[nt][1] = __expf(S[nt][1] - mn0); ls0 += S[nt][1];
      S[nt][2] = __expf(S[nt][2] - mn1); ls1 += S[nt][2];
      S[nt][3] = __expf(S[nt][3] - mn1); ls1 += S[nt][3];
    }
    ls0 += __shfl_xor_sync(0xffffffffu, ls0, 1);
    ls0 += __shfl_xor_sync(0xffffffffu, ls0, 2);
    ls1 += __shfl_xor_sync(0xffffffffu, ls1, 1);
    ls1 += __shfl_xor_sync(0xffffffffu, ls1, 2);
    l0r = l0r * al0 + ls0;
    l1r = l1r * al1 + ls1;
    #pragma unroll
    for (int nt = 0; nt < 8; nt++) {
      O[nt][0] *= al0; O[nt][1] *= al0;
      O[nt][2] *= al1; O[nt][3] *= al1;
    }

    // O += P V (3-pass); P fragments come straight from S registers
    #pragma unroll
    for (int kc = 0; kc < 4; kc++) {
      uint32_t a0h, a0l, a1h, a1l, a2h, a2l, a3h, a3l;
      split2(S[2*kc][0],   S[2*kc][1],   a0h, a0l);
      split2(S[2*kc][2],   S[2*kc][3],   a1h, a1l);
      split2(S[2*kc+1][0], S[2*kc+1][1], a2h, a2l);
      split2(S[2*kc+1][2], S[2*kc+1][3], a3h, a3l);
      const int kc16 = kc * 16;
      #pragma unroll
      for (int np = 0; np < 4; np++) {
        uint32_t vh[4], vl[4];
        const uint32_t voff = (uint32_t)(((np * 16 + b_row) * 72 + kc16 + b_col) * 2);
        ldsm4(tVh + voff, vh);
        ldsm4(tVl + voff, vl);
        #pragma unroll
        for (int j = 0; j < 2; j++) {
          const int nd = np * 2 + j;
          mma_f16(O[nd], a0h, a1h, a2h, a3h, vh[2*j], vh[2*j+1]);
          mma_f16(O[nd], a0h, a1h, a2h, a3h, vl[2*j], vl[2*j+1]);
          mma_f16(O[nd], a0l, a1l, a2l, a3l, vh[2*j], vh[2*j+1]);
        }
      }
    }
    __syncthreads();
  }

  // epilogue: normalize, split-write to g_Ah/g_Al at [b*TT + t][h*64 + d]
  const float inv0 = 1.f / l0r, inv1 = 1.f / l1r;
  const int colb = (bh & 15) * DH;
  const size_t orow0 = (size_t)(bh >> 4) * TT + row0g;
  const size_t orow1 = orow0 + 8;
  #pragma unroll
  for (int nd = 0; nd < 8; nd++) {
    const int d0 = nd * 8 + 2 * q;
    const size_t i00 = orow0 * EE + colb + d0;
    const size_t i10 = orow1 * EE + colb + d0;
    store_split(g_Ah, g_Al, i00,     O[nd][0] * inv0);
    store_split(g_Ah, g_Al, i00 + 1, O[nd][1] * inv0);
    store_split(g_Ah, g_Al, i10,     O[nd][2] * inv1);
    store_split(g_Ah, g_Al, i10 + 1, O[nd][3] * inv1);
  }
}

// ---------------------------------------------------------------------------
extern "C" void kernel_launch(void* const* d_in, const int* in_sizes, int n_in,
                              void* d_out, int out_size) {
  const float* x  = (const float*)d_in[0];
  const float* Wq = (const float*)d_in[1];
  const float* Wk = (const float*)d_in[2];
  const float* Wv = (const float*)d_in[3];
  const float* Wo = (const float*)d_in[4];
  const float* wb = (const float*)d_in[5];
  float* out = (float*)d_out;

  __half *xh, *xl, *wth, *wtl, *woh, *wol, *ah, *al;
  cudaGetSymbolAddress((void**)&xh, g_xh);   cudaGetSymbolAddress((void**)&xl, g_xl);
  cudaGetSymbolAddress((void**)&wth, g_Wth); cudaGetSymbolAddress((void**)&wtl, g_Wtl);
  cudaGetSymbolAddress((void**)&woh, g_Woh); cudaGetSymbolAddress((void**)&wol, g_Wol);
  cudaGetSymbolAddress((void**)&ah, g_Ah);   cudaGetSymbolAddress((void**)&al, g_Al);

  cudaFuncSetAttribute(gemm_f16<0>, cudaFuncAttributeMaxDynamicSharedMemorySize, GEMM_SMEM);
  cudaFuncSetAttribute(gemm_f16<1>, cudaFuncAttributeMaxDynamicSharedMemorySize, GEMM_SMEM);
  cudaFuncSetAttribute(attn_f16, cudaFuncAttributeMaxDynamicSharedMemorySize, ATT_SMEM);

  split_f32<<<(MTOT*EE/4 + 255)/256, 256>>>(x, xh, xl, MTOT*EE/4);
  split_f32<<<(EE*EE/4 + 255)/256, 256>>>(Wo, woh, wol, EE*EE/4);
  transpose_w<<<dim3(EE/32, DH/32, 48), dim3(32, 8)>>>(Wq, Wk, Wv);

  gemm_f16<0><<<dim3(3*EE/128, MTOT/128), 256, GEMM_SMEM>>>(xh, xl, wth, wtl, nullptr, nullptr);

  attn_f16<<<dim3(TT/128, BHN), 256, ATT_SMEM>>>();

  gemm_f16<1><<<dim3(EE/128, MTOT/128), 256, GEMM_SMEM>>>(ah, al, woh, wol, wb, out);
}

// round 7
// speedup vs baseline: 3.8176x; 1.4053x over previous
#include <cuda_runtime.h>
#include <cuda_fp16.h>
#include <cstdint>

#define BB 2
#define TT 2048
#define EE 1024
#define HH 16
#define DH 64
#define MTOT (BB*TT)   // 4096
#define BHN (BB*HH)    // 32

// ---------------------------------------------------------------------------
// Global scratch. B-side operands keep hi/lo split; activations are fp16 (hi).
// ---------------------------------------------------------------------------
__device__ __align__(128) __half g_xh[(size_t)MTOT*EE];
__device__ __align__(128) __half g_Wth[(size_t)3*EE*EE];   // [3072][1024]
__device__ __align__(128) __half g_Wtl[(size_t)3*EE*EE];
__device__ __align__(128) __half g_Qh[(size_t)BHN*TT*DH];  // [bh][t][d]
__device__ __align__(128) __half g_Kh[(size_t)BHN*TT*DH];  // [bh][t][d]
__device__ __align__(128) __half g_Kl[(size_t)BHN*TT*DH];
__device__ __align__(128) __half g_Vth[(size_t)BHN*TT*DH]; // [bh][d][t]
__device__ __align__(128) __half g_Vtl[(size_t)BHN*TT*DH];
__device__ __align__(128) __half g_Ah[(size_t)MTOT*EE];    // attn out
__device__ __align__(128) __half g_Woh[(size_t)EE*EE];     // [out][in]
__device__ __align__(128) __half g_Wol[(size_t)EE*EE];

// ---------------------------------------------------------------------------
// Helpers
// ---------------------------------------------------------------------------
__device__ __forceinline__ uint32_t smem_u32(const void* p) {
  uint32_t a;
  asm("{ .reg .u64 t; cvta.to.shared.u64 t, %1; cvt.u32.u64 %0, t; }" : "=r"(a) : "l"(p));
  return a;
}
__device__ __forceinline__ void ldsm4(uint32_t addr, uint32_t r[4]) {
  asm volatile("ldmatrix.sync.aligned.m8n8.x4.shared.b16 {%0,%1,%2,%3}, [%4];"
               : "=r"(r[0]), "=r"(r[1]), "=r"(r[2]), "=r"(r[3]) : "r"(addr));
}
__device__ __forceinline__ void cp16(uint32_t dst, const void* src) {
  asm volatile("cp.async.ca.shared.global [%0], [%1], 16;" :: "r"(dst), "l"(src) : "memory");
}
__device__ __forceinline__ void cp_commit() {
  asm volatile("cp.async.commit_group;" ::: "memory");
}
template<int N> __device__ __forceinline__ void cp_wait() {
  asm volatile("cp.async.wait_group %0;" :: "n"(N) : "memory");
}
__device__ __forceinline__ void f16_split(float x, __half& h, __half& l) {
  h = __float2half_rn(x);
  l = __float2half_rn(x - __half2float(h));
}
__device__ __forceinline__ void store_split(__half* H, __half* L, size_t idx, float v) {
  __half h, l; f16_split(v, h, l);
  H[idx] = h; L[idx] = l;
}
__device__ __forceinline__ uint32_t pack2(float a, float b) {  // a -> low half
  __half2 h = __floats2half2_rn(a, b);
  return *(uint32_t*)&h;
}
__device__ __forceinline__ void mma_f16(float c[4], uint32_t a0, uint32_t a1,
                                        uint32_t a2, uint32_t a3,
                                        uint32_t b0, uint32_t b1) {
  asm volatile(
    "mma.sync.aligned.m16n8k16.row.col.f32.f16.f16.f32 "
    "{%0,%1,%2,%3},{%4,%5,%6,%7},{%8,%9},{%0,%1,%2,%3};"
    : "+f"(c[0]), "+f"(c[1]), "+f"(c[2]), "+f"(c[3])
    : "r"(a0), "r"(a1), "r"(a2), "r"(a3), "r"(b0), "r"(b1));
}

// ---------------------------------------------------------------------------
// Conversions
// ---------------------------------------------------------------------------
__global__ __launch_bounds__(256) void conv_h(const float* __restrict__ s,
                                              __half* __restrict__ H, int n4) {
  int i = blockIdx.x * 256 + threadIdx.x;
  if (i >= n4) return;
  float4 v = ((const float4*)s)[i];
  __half2* Hp = (__half2*)(H + (size_t)i*4);
  Hp[0] = __floats2half2_rn(v.x, v.y);
  Hp[1] = __floats2half2_rn(v.z, v.w);
}
__global__ __launch_bounds__(256) void split_f32(const float* __restrict__ s,
                                                 __half* __restrict__ H,
                                                 __half* __restrict__ L, int n4) {
  int i = blockIdx.x * 256 + threadIdx.x;
  if (i >= n4) return;
  float4 v = ((const float4*)s)[i];
  __half h0,l0,h1,l1,h2,l2,h3,l3;
  f16_split(v.x,h0,l0); f16_split(v.y,h1,l1); f16_split(v.z,h2,l2); f16_split(v.w,h3,l3);
  __half2* Hp = (__half2*)(H + (size_t)i*4);
  __half2* Lp = (__half2*)(L + (size_t)i*4);
  Hp[0] = __halves2half2(h0,h1); Hp[1] = __halves2half2(h2,h3);
  Lp[0] = __halves2half2(l0,l1); Lp[1] = __halves2half2(l2,l3);
}

// ---------------------------------------------------------------------------
// Weight transpose+split: g_Wth/l[(p*16+h)*64 + d][e] = W_p[h][e][d]
// ---------------------------------------------------------------------------
__global__ __launch_bounds__(256) void transpose_w(
    const float* __restrict__ Wq, const float* __restrict__ Wk,
    const float* __restrict__ Wv) {
  __shared__ float t[32][33];
  const int bz = blockIdx.z;
  const int p = bz >> 4;
  const float* W = (p == 0 ? Wq : p == 1 ? Wk : Wv) + (size_t)(bz & 15) * EE * DH;
  const int e0 = blockIdx.x * 32;
  const int d0 = blockIdx.y * 32;
  const int tx = threadIdx.x, ty = threadIdx.y;
  #pragma unroll
  for (int i = ty; i < 32; i += 8)
    t[i][tx] = W[(size_t)(e0 + i) * DH + d0 + tx];
  __syncthreads();
  #pragma unroll
  for (int i = ty; i < 32; i += 8) {
    size_t idx = (size_t)(bz * DH + d0 + i) * EE + e0 + tx;
    store_split(g_Wth, g_Wtl, idx, t[tx][i]);
  }
}

// ---------------------------------------------------------------------------
// fp16 2-pass GEMM (A rounded, B split). BM=128 BN=128 BK=32, 256 thr,
// 3-stage cp.async pipeline, ONE barrier per k-iter, ldmatrix frags.
// ---------------------------------------------------------------------------
#define NKIT (EE / 32)                // 32
#define G_TILE_H 5120                 // halves per 128x40 tile
#define G_STAGE_B (3 * G_TILE_H * 2)  // 30720 bytes (Ah,Bh,Bl)
#define GEMM_SMEM (3 * G_STAGE_B)     // 92160

template<int MODE>
__global__ __launch_bounds__(256, 2) void gemm_f16(
    const __half* __restrict__ pAh, const __half* __restrict__ pBh,
    const __half* __restrict__ pBl,
    const float* __restrict__ bias, float* __restrict__ outp) {
  extern __shared__ __align__(16) char gsm[];
  const int tid = threadIdx.x;
  const int lane = tid & 31, q = lane & 3, g = lane >> 2;
  const int wid = tid >> 5, wm = wid >> 2, wn = wid & 3;
  const int n0 = blockIdx.x * 128;
  const size_t m0 = (size_t)blockIdx.y * 128;
  const uint32_t s0 = smem_u32(gsm);

  const int a_row = lane & 15;
  const int a_col = (lane >> 4) << 3;
  const int b_row = (lane & 7) + ((lane >> 4) << 3);
  const int b_col = ((lane >> 3) & 1) << 3;

  float C[4][4][4];
  #pragma unroll
  for (int a = 0; a < 4; a++)
    #pragma unroll
    for (int b = 0; b < 4; b++)
      #pragma unroll
      for (int c = 0; c < 4; c++) C[a][b][c] = 0.f;

  auto issue = [&](int stage, int k0) {
    const uint32_t sb = s0 + (uint32_t)stage * G_STAGE_B;
    #pragma unroll
    for (int t = 0; t < 6; t++) {
      int c = tid + t * 256;           // 0..1535
      int arr = c >> 9, rem = c & 511;
      int row = rem >> 2, seg = rem & 3;
      const __half* src;
      if (arr == 0)      src = pAh + (m0 + row) * EE + k0 + seg * 8;
      else if (arr == 1) src = pBh + (size_t)(n0 + row) * EE + k0 + seg * 8;
      else               src = pBl + (size_t)(n0 + row) * EE + k0 + seg * 8;
      cp16(sb + (uint32_t)(arr * G_TILE_H + row * 40 + seg * 8) * 2, src);
    }
    cp_commit();
  };

  issue(0, 0);
  issue(1, 32);
  cp_wait<1>(); __syncthreads();

  for (int i = 0; i < NKIT; i++) {
    if (i + 2 < NKIT) issue((i + 2) % 3, (i + 2) * 32);
    const uint32_t sb = s0 + (uint32_t)(i % 3) * G_STAGE_B;
    const uint32_t tAh = sb, tBh = sb + G_TILE_H*2, tBl = sb + 2*G_TILE_H*2;
    #pragma unroll
    for (int kc = 0; kc < 2; kc++) {
      const int kc16 = kc * 16;
      uint32_t ah[4][4];
      #pragma unroll
      for (int mt = 0; mt < 4; mt++) {
        const uint32_t off = (uint32_t)(((wm * 64 + mt * 16 + a_row) * 40 + kc16 + a_col) * 2);
        ldsm4(tAh + off, ah[mt]);
      }
      uint32_t bhf[2][4], blf[2][4];
      #pragma unroll
      for (int np = 0; np < 2; np++) {
        const uint32_t off = (uint32_t)(((wn * 32 + np * 16 + b_row) * 40 + kc16 + b_col) * 2);
        ldsm4(tBh + off, bhf[np]);
        ldsm4(tBl + off, blf[np]);
      }
      #pragma unroll
      for (int np = 0; np < 2; np++) {
        #pragma unroll
        for (int j = 0; j < 2; j++) {
          const int nt = np * 2 + j;
          #pragma unroll
          for (int mt = 0; mt < 4; mt++) {
            mma_f16(C[mt][nt], ah[mt][0], ah[mt][1], ah[mt][2], ah[mt][3],
                    bhf[np][2*j], bhf[np][2*j+1]);
            mma_f16(C[mt][nt], ah[mt][0], ah[mt][1], ah[mt][2], ah[mt][3],
                    blf[np][2*j], blf[np][2*j+1]);
          }
        }
      }
    }
    if (i + 1 < NKIT) {
      if (i + 2 < NKIT) cp_wait<1>(); else cp_wait<0>();
      __syncthreads();
    }
  }

  // epilogue
  #pragma unroll
  for (int mt = 0; mt < 4; mt++) {
    #pragma unroll
    for (int nt = 0; nt < 4; nt++) {
      #pragma unroll
      for (int e = 0; e < 4; e++) {
        const int r = (int)m0 + wm * 64 + mt * 16 + g + (e >= 2 ? 8 : 0);
        const int c = n0 + wn * 32 + nt * 8 + 2 * q + (e & 1);
        const float v = C[mt][nt][e];
        if (MODE == 0) {
          const int p = c >> 10, rl = c & 1023, hh = rl >> 6, d = rl & 63;
          const int bhi = (r >> 11) * HH + hh, t = r & (TT - 1);
          if (p == 2) {
            store_split(g_Vth, g_Vtl, ((size_t)bhi * DH + d) * TT + t, v);
          } else if (p == 1) {
            store_split(g_Kh, g_Kl, ((size_t)bhi * TT + t) * DH + d, v);
          } else {
            g_Qh[((size_t)bhi * TT + t) * DH + d] = __float2half_rn(v);
          }
        } else {
          outp[(size_t)r * EE + c] = v + bias[c];
        }
      }
    }
  }
}

// ---------------------------------------------------------------------------
// fp16 2-pass flash attention (Q,P rounded; K,V split). One barrier per block.
// ---------------------------------------------------------------------------
#define AT_Q_H   9216       // 128*72
#define AT_T_H   4608       // 64*72
#define AT_KV_H  (4 * AT_T_H)
#define ATT_SMEM ((AT_Q_H + 2 * AT_KV_H) * 2)   // 92160 bytes

__global__ __launch_bounds__(256, 2) void attn_f16() {
  extern __shared__ __align__(16) char asm_[];
  const int tid = threadIdx.x;
  const int lane = tid & 31, q = lane & 3, g = lane >> 2;
  const int wid = tid >> 5;
  const int i0 = ((int)gridDim.x - 1 - (int)blockIdx.x) * 128;  // heavy CTAs first
  const int bh = blockIdx.y;
  const uint32_t s0 = smem_u32(asm_);
  const uint32_t pQh = s0;
  const uint32_t kvBase = s0 + AT_Q_H * 2;

  const int a_row = lane & 15;
  const int a_col = (lane >> 4) << 3;
  const int b_row = (lane & 7) + ((lane >> 4) << 3);
  const int b_col = ((lane >> 3) & 1) << 3;

  // Q (hi only): 128 rows x 8 segs = 1024 float4s
  #pragma unroll
  for (int t = 0; t < 4; t++) {
    int c = tid + t * 256;
    int row = c >> 3, seg = c & 7;
    const __half* src = g_Qh + ((size_t)bh * TT + i0 + row) * DH + seg * 8;
    cp16(pQh + (uint32_t)(row * 72 + seg * 8) * 2, src);
  }
  auto issue_kv = [&](int stage, int j0) {
    const uint32_t kb = kvBase + (uint32_t)stage * AT_KV_H * 2;
    #pragma unroll
    for (int t = 0; t < 8; t++) {
      int c = tid + t * 256;
      int arr = c >> 9, rem = c & 511, row = rem >> 3, seg = rem & 7;
      const __half* src;
      if (arr == 0)      src = g_Kh  + ((size_t)bh * TT + j0 + row) * DH + seg * 8;
      else if (arr == 1) src = g_Kl  + ((size_t)bh * TT + j0 + row) * DH + seg * 8;
      else if (arr == 2) src = g_Vth + ((size_t)bh * DH + row) * TT + j0 + seg * 8;
      else               src = g_Vtl + ((size_t)bh * DH + row) * TT + j0 + seg * 8;
      cp16(kb + (uint32_t)(arr * AT_T_H + row * 72 + seg * 8) * 2, src);
    }
    cp_commit();
  };

  const int nb = i0 / 64 + 2;
  issue_kv(0, 0);             // Q cp.asyncs join this group
  cp_wait<0>(); __syncthreads();

  float O[8][4];
  #pragma unroll
  for (int a = 0; a < 8; a++)
    #pragma unroll
    for (int e = 0; e < 4; e++) O[a][e] = 0.f;
  float m0r = -1e30f, m1r = -1e30f, l0r = 0.f, l1r = 0.f;
  const int row0g = i0 + wid * 16 + g;
  const int row1g = row0g + 8;

  for (int jb = 0; jb < nb; jb++) {
    if (jb + 1 < nb) issue_kv((jb + 1) & 1, (jb + 1) * 64);
    const uint32_t kb = kvBase + (uint32_t)(jb & 1) * AT_KV_H * 2;
    const uint32_t tKh = kb, tKl = kb + AT_T_H*2, tVh = kb + 2*AT_T_H*2, tVl = kb + 3*AT_T_H*2;

    // S = Q K^T (2-pass: Q rounded, K split)
    float S[8][4];
    #pragma unroll
    for (int a = 0; a < 8; a++)
      #pragma unroll
      for (int e = 0; e < 4; e++) S[a][e] = 0.f;
    #pragma unroll
    for (int kc = 0; kc < 4; kc++) {
      const int kc16 = kc * 16;
      uint32_t qh[4];
      const uint32_t qoff = (uint32_t)(((wid * 16 + a_row) * 72 + kc16 + a_col) * 2);
      ldsm4(pQh + qoff, qh);
      #pragma unroll
      for (int np = 0; np < 4; np++) {
        uint32_t kh[4], kl[4];
        const uint32_t koff = (uint32_t)(((np * 16 + b_row) * 72 + kc16 + b_col) * 2);
        ldsm4(tKh + koff, kh);
        ldsm4(tKl + koff, kl);
        #pragma unroll
        for (int j = 0; j < 2; j++) {
          const int nt = np * 2 + j;
          mma_f16(S[nt], qh[0], qh[1], qh[2], qh[3], kh[2*j], kh[2*j+1]);
          mma_f16(S[nt], qh[0], qh[1], qh[2], qh[3], kl[2*j], kl[2*j+1]);
        }
      }
    }

    // scale + causal mask
    const int j0 = jb * 64;
    #pragma unroll
    for (int nt = 0; nt < 8; nt++)
      #pragma unroll
      for (int e = 0; e < 4; e++) S[nt][e] *= 0.125f;
    if (j0 >= i0) {
      #pragma unroll
      for (int nt = 0; nt < 8; nt++) {
        const int cb = j0 + nt * 8 + 2 * q;
        if (cb     > row0g) S[nt][0] = -1e30f;
        if (cb + 1 > row0g) S[nt][1] = -1e30f;
        if (cb     > row1g) S[nt][2] = -1e30f;
        if (cb + 1 > row1g) S[nt][3] = -1e30f;
      }
    }

    // online softmax
    float mx0 = -1e30f, mx1 = -1e30f;
    #pragma unroll
    for (int nt = 0; nt < 8; nt++) {
      mx0 = fmaxf(mx0, fmaxf(S[nt][0], S[nt][1]));
      mx1 = fmaxf(mx1, fmaxf(S[nt][2], S[nt][3]));
    }
    mx0 = fmaxf(mx0, __shfl_xor_sync(0xffffffffu, mx0, 1));
    mx0 = fmaxf(mx0, __shfl_xor_sync(0xffffffffu, mx0, 2));
    mx1 = fmaxf(mx1, __shfl_xor_sync(0xffffffffu, mx1, 1));
    mx1 = fmaxf(mx1, __shfl_xor_sync(0xffffffffu, mx1, 2));
    const float mn0 = fmaxf(m0r, mx0), mn1 = fmaxf(m1r, mx1);
    const float al0 = __expf(m0r - mn0), al1 = __expf(m1r - mn1);
    m0r = mn0; m1r = mn1;
    float ls0 = 0.f, ls1 = 0.f;
    #pragma unroll
    for (int nt = 0; nt < 8; nt++) {
      S[nt][0] = __expf(S[nt][0] - mn0); ls0 += S[nt][0];
      S[nt][1] = __expf(S[nt][1] - mn0); ls0 += S[nt][1];
      S[nt][2] = __expf(S[nt][2] - mn1); ls1 += S[nt][2];
      S[nt][3] = __expf(S[nt][3] - mn1); ls1 += S[nt][3];
    }
    ls0 += __shfl_xor_sync(0xffffffffu, ls0, 1);
    ls0 += __shfl_xor_sync(0xffffffffu, ls0, 2);
    ls1 += __shfl_xor_sync(0xffffffffu, ls1, 1);
    ls1 += __shfl_xor_sync(0xffffffffu, ls1, 2);
    l0r = l0r * al0 + ls0;
    l1r = l1r * al1 + ls1;
    #pragma unroll
    for (int nt = 0; nt < 8; nt++) {
      O[nt][0] *= al0; O[nt][1] *= al0;
      O[nt][2] *= al1; O[nt][3] *= al1;
    }

    // O += P V (2-pass: P rounded, V split)
    #pragma unroll
    for (int kc = 0; kc < 4; kc++) {
      const uint32_t a0 = pack2(S[2*kc][0],   S[2*kc][1]);
      const uint32_t a1 = pack2(S[2*kc][2],   S[2*kc][3]);
      const uint32_t a2 = pack2(S[2*kc+1][0], S[2*kc+1][1]);
      const uint32_t a3 = pack2(S[2*kc+1][2], S[2*kc+1][3]);
      const int kc16 = kc * 16;
      #pragma unroll
      for (int np = 0; np < 4; np++) {
        uint32_t vh[4], vl[4];
        const uint32_t voff = (uint32_t)(((np * 16 + b_row) * 72 + kc16 + b_col) * 2);
        ldsm4(tVh + voff, vh);
        ldsm4(tVl + voff, vl);
        #pragma unroll
        for (int j = 0; j < 2; j++) {
          const int nd = np * 2 + j;
          mma_f16(O[nd], a0, a1, a2, a3, vh[2*j], vh[2*j+1]);
          mma_f16(O[nd], a0, a1, a2, a3, vl[2*j], vl[2*j+1]);
        }
      }
    }
    if (jb + 1 < nb) { cp_wait<0>(); __syncthreads(); }
  }

  // epilogue: normalize, write hi-only to g_Ah at [b*TT + t][h*64 + d]
  const float inv0 = 1.f / l0r, inv1 = 1.f / l1r;
  const int colb = (bh & 15) * DH;
  const size_t orow0 = (size_t)(bh >> 4) * TT + row0g;
  const size_t orow1 = orow0 + 8;
  #pragma unroll
  for (int nd = 0; nd < 8; nd++) {
    const int d0 = nd * 8 + 2 * q;
    __half2* p0 = (__half2*)&g_Ah[orow0 * EE + colb + d0];
    __half2* p1 = (__half2*)&g_Ah[orow1 * EE + colb + d0];
    *p0 = __floats2half2_rn(O[nd][0] * inv0, O[nd][1] * inv0);
    *p1 = __floats2half2_rn(O[nd][2] * inv1, O[nd][3] * inv1);
  }
}

// ---------------------------------------------------------------------------
extern "C" void kernel_launch(void* const* d_in, const int* in_sizes, int n_in,
                              void* d_out, int out_size) {
  const float* x  = (const float*)d_in[0];
  const float* Wq = (const float*)d_in[1];
  const float* Wk = (const float*)d_in[2];
  const float* Wv = (const float*)d_in[3];
  const float* Wo = (const float*)d_in[4];
  const float* wb = (const float*)d_in[5];
  float* out = (float*)d_out;

  __half *xh, *wth, *wtl, *woh, *wol, *ah;
  cudaGetSymbolAddress((void**)&xh, g_xh);
  cudaGetSymbolAddress((void**)&wth, g_Wth); cudaGetSymbolAddress((void**)&wtl, g_Wtl);
  cudaGetSymbolAddress((void**)&woh, g_Woh); cudaGetSymbolAddress((void**)&wol, g_Wol);
  cudaGetSymbolAddress((void**)&ah, g_Ah);

  cudaFuncSetAttribute(gemm_f16<0>, cudaFuncAttributeMaxDynamicSharedMemorySize, GEMM_SMEM);
  cudaFuncSetAttribute(gemm_f16<1>, cudaFuncAttributeMaxDynamicSharedMemorySize, GEMM_SMEM);
  cudaFuncSetAttribute(attn_f16, cudaFuncAttributeMaxDynamicSharedMemorySize, ATT_SMEM);

  conv_h<<<(MTOT*EE/4 + 255)/256, 256>>>(x, xh, MTOT*EE/4);
  split_f32<<<(EE*EE/4 + 255)/256, 256>>>(Wo, woh, wol, EE*EE/4);
  transpose_w<<<dim3(EE/32, DH/32, 48), dim3(32, 8)>>>(Wq, Wk, Wv);

  gemm_f16<0><<<dim3(3*EE/128, MTOT/128), 256, GEMM_SMEM>>>(xh, wth, wtl, nullptr, nullptr);

  attn_f16<<<dim3(TT/128, BHN), 256, ATT_SMEM>>>();

  gemm_f16<1><<<dim3(EE/128, MTOT/128), 256, GEMM_SMEM>>>(ah, woh, wol, wb, out);
}

// round 9
// speedup vs baseline: 4.3647x; 1.1433x over previous
#include <cuda_runtime.h>
#include <cuda_fp16.h>
#include <cstdint>

#define BB 2
#define TT 2048
#define EE 1024
#define HH 16
#define DH 64
#define MTOT (BB*TT)   // 4096
#define BHN (BB*HH)    // 32

// ---------------------------------------------------------------------------
// Global scratch. QKV weights + K keep hi/lo split; V, Wo, activations rounded.
// ---------------------------------------------------------------------------
__device__ __align__(128) __half g_xh[(size_t)MTOT*EE];
__device__ __align__(128) __half g_Wth[(size_t)3*EE*EE];   // [3072][1024]
__device__ __align__(128) __half g_Wtl[(size_t)3*EE*EE];
__device__ __align__(128) __half g_Qh[(size_t)BHN*TT*DH];  // [bh][t][d] (x0.125)
__device__ __align__(128) __half g_Kh[(size_t)BHN*TT*DH];  // [bh][t][d]
__device__ __align__(128) __half g_Kl[(size_t)BHN*TT*DH];
__device__ __align__(128) __half g_Vt[(size_t)BHN*TT*DH];  // [bh][d][t]
__device__ __align__(128) __half g_Ah[(size_t)MTOT*EE];    // attn out
__device__ __align__(128) __half g_Woh[(size_t)EE*EE];     // [out][in]

// ---------------------------------------------------------------------------
// Helpers
// ---------------------------------------------------------------------------
__device__ __forceinline__ uint32_t smem_u32(const void* p) {
  uint32_t a;
  asm("{ .reg .u64 t; cvta.to.shared.u64 t, %1; cvt.u32.u64 %0, t; }" : "=r"(a) : "l"(p));
  return a;
}
__device__ __forceinline__ void ldsm4(uint32_t addr, uint32_t r[4]) {
  asm volatile("ldmatrix.sync.aligned.m8n8.x4.shared.b16 {%0,%1,%2,%3}, [%4];"
               : "=r"(r[0]), "=r"(r[1]), "=r"(r[2]), "=r"(r[3]) : "r"(addr));
}
__device__ __forceinline__ void cp16(uint32_t dst, const void* src) {
  asm volatile("cp.async.ca.shared.global [%0], [%1], 16;" :: "r"(dst), "l"(src) : "memory");
}
__device__ __forceinline__ void cp_commit() {
  asm volatile("cp.async.commit_group;" ::: "memory");
}
template<int N> __device__ __forceinline__ void cp_wait() {
  asm volatile("cp.async.wait_group %0;" :: "n"(N) : "memory");
}
__device__ __forceinline__ void f16_split(float x, __half& h, __half& l) {
  h = __float2half_rn(x);
  l = __float2half_rn(x - __half2float(h));
}
__device__ __forceinline__ void store_split(__half* H, __half* L, size_t idx, float v) {
  __half h, l; f16_split(v, h, l);
  H[idx] = h; L[idx] = l;
}
__device__ __forceinline__ uint32_t pack2(float a, float b) {  // a -> low half
  __half2 h = __floats2half2_rn(a, b);
  return *(uint32_t*)&h;
}
__device__ __forceinline__ void mma_f16(float c[4], uint32_t a0, uint32_t a1,
                                        uint32_t a2, uint32_t a3,
                                        uint32_t b0, uint32_t b1) {
  asm volatile(
    "mma.sync.aligned.m16n8k16.row.col.f32.f16.f16.f32 "
    "{%0,%1,%2,%3},{%4,%5,%6,%7},{%8,%9},{%0,%1,%2,%3};"
    : "+f"(c[0]), "+f"(c[1]), "+f"(c[2]), "+f"(c[3])
    : "r"(a0), "r"(a1), "r"(a2), "r"(a3), "r"(b0), "r"(b1));
}

// ---------------------------------------------------------------------------
// Conversions
// ---------------------------------------------------------------------------
__global__ __launch_bounds__(256) void conv_h(const float* __restrict__ s,
                                              __half* __restrict__ H, int n4) {
  int i = blockIdx.x * 256 + threadIdx.x;
  if (i >= n4) return;
  float4 v = ((const float4*)s)[i];
  __half2* Hp = (__half2*)(H + (size_t)i*4);
  Hp[0] = __floats2half2_rn(v.x, v.y);
  Hp[1] = __floats2half2_rn(v.z, v.w);
}

// ---------------------------------------------------------------------------
// Weight transpose+split (QKV): g_Wth/l[(p*16+h)*64 + d][e] = W_p[h][e][d]
// ---------------------------------------------------------------------------
__global__ __launch_bounds__(256) void transpose_w(
    const float* __restrict__ Wq, const float* __restrict__ Wk,
    const float* __restrict__ Wv) {
  __shared__ float t[32][33];
  const int bz = blockIdx.z;
  const int p = bz >> 4;
  const float* W = (p == 0 ? Wq : p == 1 ? Wk : Wv) + (size_t)(bz & 15) * EE * DH;
  const int e0 = blockIdx.x * 32;
  const int d0 = blockIdx.y * 32;
  const int tx = threadIdx.x, ty = threadIdx.y;
  #pragma unroll
  for (int i = ty; i < 32; i += 8)
    t[i][tx] = W[(size_t)(e0 + i) * DH + d0 + tx];
  __syncthreads();
  #pragma unroll
  for (int i = ty; i < 32; i += 8) {
    size_t idx = (size_t)(bz * DH + d0 + i) * EE + e0 + tx;
    store_split(g_Wth, g_Wtl, idx, t[tx][i]);
  }
}

// ---------------------------------------------------------------------------
// fp16 GEMM. BM=128 BN=128 BK=32, 256 thr, 3-stage cp.async, 1 barrier/iter.
// SPLITB=1: B hi/lo 2-pass (QKV). SPLITB=0: B rounded single pass (O-proj).
// ---------------------------------------------------------------------------
#define NKIT (EE / 32)                // 32
#define G_TILE_H 5120                 // halves per 128x40 tile
#define GEMM_SMEM_SPLIT (3 * 3 * G_TILE_H * 2)   // 92160
#define GEMM_SMEM_PLAIN (3 * 2 * G_TILE_H * 2)   // 61440

template<int MODE, int SPLITB>
__global__ __launch_bounds__(256, 2) void gemm_f16(
    const __half* __restrict__ pAh, const __half* __restrict__ pBh,
    const __half* __restrict__ pBl,
    const float* __restrict__ bias, float* __restrict__ outp) {
  extern __shared__ __align__(16) char gsm[];
  constexpr int NTILE = SPLITB ? 3 : 2;
  constexpr uint32_t STAGE_B = NTILE * G_TILE_H * 2;
  const int tid = threadIdx.x;
  const int lane = tid & 31, q = lane & 3, g = lane >> 2;
  const int wid = tid >> 5, wm = wid >> 2, wn = wid & 3;
  const int n0 = blockIdx.x * 128;
  const size_t m0 = (size_t)blockIdx.y * 128;
  const uint32_t s0 = smem_u32(gsm);

  const int a_row = lane & 15;
  const int a_col = (lane >> 4) << 3;
  const int b_row = (lane & 7) + ((lane >> 4) << 3);
  const int b_col = ((lane >> 3) & 1) << 3;

  float C[4][4][4];
  #pragma unroll
  for (int a = 0; a < 4; a++)
    #pragma unroll
    for (int b = 0; b < 4; b++)
      #pragma unroll
      for (int c = 0; c < 4; c++) C[a][b][c] = 0.f;

  auto issue = [&](int stage, int k0) {
    const uint32_t sb = s0 + (uint32_t)stage * STAGE_B;
    #pragma unroll
    for (int t = 0; t < 2 * NTILE; t++) {
      int c = tid + t * 256;
      int arr = c >> 9, rem = c & 511;
      int row = rem >> 2, seg = rem & 3;
      const __half* src;
      if (arr == 0)      src = pAh + (m0 + row) * EE + k0 + seg * 8;
      else if (arr == 1) src = pBh + (size_t)(n0 + row) * EE + k0 + seg * 8;
      else               src = pBl + (size_t)(n0 + row) * EE + k0 + seg * 8;
      cp16(sb + (uint32_t)(arr * G_TILE_H + row * 40 + seg * 8) * 2, src);
    }
    cp_commit();
  };

  issue(0, 0);
  issue(1, 32);
  cp_wait<1>(); __syncthreads();

  for (int i = 0; i < NKIT; i++) {
    if (i + 2 < NKIT) issue((i + 2) % 3, (i + 2) * 32);
    const uint32_t sb = s0 + (uint32_t)(i % 3) * STAGE_B;
    const uint32_t tAh = sb, tBh = sb + G_TILE_H*2, tBl = sb + 2*G_TILE_H*2;
    #pragma unroll
    for (int kc = 0; kc < 2; kc++) {
      const int kc16 = kc * 16;
      uint32_t ah[4][4];
      #pragma unroll
      for (int mt = 0; mt < 4; mt++) {
        const uint32_t off = (uint32_t)(((wm * 64 + mt * 16 + a_row) * 40 + kc16 + a_col) * 2);
        ldsm4(tAh + off, ah[mt]);
      }
      uint32_t bhf[2][4], blf[2][4];
      #pragma unroll
      for (int np = 0; np < 2; np++) {
        const uint32_t off = (uint32_t)(((wn * 32 + np * 16 + b_row) * 40 + kc16 + b_col) * 2);
        ldsm4(tBh + off, bhf[np]);
        if (SPLITB) ldsm4(tBl + off, blf[np]);
      }
      #pragma unroll
      for (int np = 0; np < 2; np++) {
        #pragma unroll
        for (int j = 0; j < 2; j++) {
          const int nt = np * 2 + j;
          #pragma unroll
          for (int mt = 0; mt < 4; mt++) {
            mma_f16(C[mt][nt], ah[mt][0], ah[mt][1], ah[mt][2], ah[mt][3],
                    bhf[np][2*j], bhf[np][2*j+1]);
            if (SPLITB)
              mma_f16(C[mt][nt], ah[mt][0], ah[mt][1], ah[mt][2], ah[mt][3],
                      blf[np][2*j], blf[np][2*j+1]);
          }
        }
      }
    }
    if (i + 1 < NKIT) {
      if (i + 2 < NKIT) cp_wait<1>(); else cp_wait<0>();
      __syncthreads();
    }
  }

  // epilogue
  #pragma unroll
  for (int mt = 0; mt < 4; mt++) {
    #pragma unroll
    for (int nt = 0; nt < 4; nt++) {
      #pragma unroll
      for (int e = 0; e < 4; e++) {
        const int r = (int)m0 + wm * 64 + mt * 16 + g + (e >= 2 ? 8 : 0);
        const int c = n0 + wn * 32 + nt * 8 + 2 * q + (e & 1);
        const float v = C[mt][nt][e];
        if (MODE == 0) {
          const int p = c >> 10, rl = c & 1023, hh = rl >> 6, d = rl & 63;
          const int bhi = (r >> 11) * HH + hh, t = r & (TT - 1);
          if (p == 2) {
            g_Vt[((size_t)bhi * DH + d) * TT + t] = __float2half_rn(v);
          } else if (p == 1) {
            store_split(g_Kh, g_Kl, ((size_t)bhi * TT + t) * DH + d, v);
          } else {
            g_Qh[((size_t)bhi * TT + t) * DH + d] = __float2half_rn(v * 0.125f);
          }
        } else {
          outp[(size_t)r * EE + c] = v + bias[c];
        }
      }
    }
  }
}

// ---------------------------------------------------------------------------
// fp16 flash attention: QK 2-pass (K split), PV single pass (V rounded).
// Q pre-scaled by 0.125. One barrier per KV block.
// ---------------------------------------------------------------------------
#define AT_Q_H   9216       // 128*72
#define AT_T_H   4608       // 64*72
#define AT_KV_H  (3 * AT_T_H)
#define ATT_SMEM ((AT_Q_H + 2 * AT_KV_H) * 2)   // 73728 bytes

__global__ __launch_bounds__(256, 2) void attn_f16() {
  extern __shared__ __align__(16) char asm_[];
  const int tid = threadIdx.x;
  const int lane = tid & 31, q = lane & 3, g = lane >> 2;
  const int wid = tid >> 5;
  const int i0 = ((int)gridDim.x - 1 - (int)blockIdx.x) * 128;  // heavy CTAs first
  const int bh = blockIdx.y;
  const uint32_t s0 = smem_u32(asm_);
  const uint32_t pQh = s0;
  const uint32_t kvBase = s0 + AT_Q_H * 2;

  const int a_row = lane & 15;
  const int a_col = (lane >> 4) << 3;
  const int b_row = (lane & 7) + ((lane >> 4) << 3);
  const int b_col = ((lane >> 3) & 1) << 3;

  // Q (hi only)
  #pragma unroll
  for (int t = 0; t < 4; t++) {
    int c = tid + t * 256;
    int row = c >> 3, seg = c & 7;
    const __half* src = g_Qh + ((size_t)bh * TT + i0 + row) * DH + seg * 8;
    cp16(pQh + (uint32_t)(row * 72 + seg * 8) * 2, src);
  }
  auto issue_kv = [&](int stage, int j0) {
    const uint32_t kb = kvBase + (uint32_t)stage * AT_KV_H * 2;
    #pragma unroll
    for (int t = 0; t < 6; t++) {
      int c = tid + t * 256;
      int arr = c >> 9, rem = c & 511, row = rem >> 3, seg = rem & 7;
      const __half* src;
      if (arr == 0)      src = g_Kh + ((size_t)bh * TT + j0 + row) * DH + seg * 8;
      else if (arr == 1) src = g_Kl + ((size_t)bh * TT + j0 + row) * DH + seg * 8;
      else               src = g_Vt + ((size_t)bh * DH + row) * TT + j0 + seg * 8;
      cp16(kb + (uint32_t)(arr * AT_T_H + row * 72 + seg * 8) * 2, src);
    }
    cp_commit();
  };

  const int nb = i0 / 64 + 2;
  issue_kv(0, 0);
  cp_wait<0>(); __syncthreads();

  float O[8][4];
  #pragma unroll
  for (int a = 0; a < 8; a++)
    #pragma unroll
    for (int e = 0; e < 4; e++) O[a][e] = 0.f;
  float m0r = -1e30f, m1r = -1e30f, l0r = 0.f, l1r = 0.f;
  const int row0g = i0 + wid * 16 + g;
  const int row1g = row0g + 8;

  for (int jb = 0; jb < nb; jb++) {
    if (jb + 1 < nb) issue_kv((jb + 1) & 1, (jb + 1) * 64);
    const uint32_t kb = kvBase + (uint32_t)(jb & 1) * AT_KV_H * 2;
    const uint32_t tKh = kb, tKl = kb + AT_T_H*2, tVh = kb + 2*AT_T_H*2;

    // S = Q K^T (Q rounded+prescaled, K split)
    float S[8][4];
    #pragma unroll
    for (int a = 0; a < 8; a++)
      #pragma unroll
      for (int e = 0; e < 4; e++) S[a][e] = 0.f;
    #pragma unroll
    for (int kc = 0; kc < 4; kc++) {
      const int kc16 = kc * 16;
      uint32_t qh[4];
      const uint32_t qoff = (uint32_t)(((wid * 16 + a_row) * 72 + kc16 + a_col) * 2);
      ldsm4(pQh + qoff, qh);
      #pragma unroll
      for (int np = 0; np < 4; np++) {
        uint32_t kh[4], kl[4];
        const uint32_t koff = (uint32_t)(((np * 16 + b_row) * 72 + kc16 + b_col) * 2);
        ldsm4(tKh + koff, kh);
        ldsm4(tKl + koff, kl);
        #pragma unroll
        for (int j = 0; j < 2; j++) {
          const int nt = np * 2 + j;
          mma_f16(S[nt], qh[0], qh[1], qh[2], qh[3], kh[2*j], kh[2*j+1]);
          mma_f16(S[nt], qh[0], qh[1], qh[2], qh[3], kl[2*j], kl[2*j+1]);
        }
      }
    }

    // causal mask (scale folded into Q)
    const int j0 = jb * 64;
    if (j0 >= i0) {
      #pragma unroll
      for (int nt = 0; nt < 8; nt++) {
        const int cb = j0 + nt * 8 + 2 * q;
        if (cb     > row0g) S[nt][0] = -1e30f;
        if (cb + 1 > row0g) S[nt][1] = -1e30f;
        if (cb     > row1g) S[nt][2] = -1e30f;
        if (cb + 1 > row1g) S[nt][3] = -1e30f;
      }
    }

    // online softmax
    float mx0 = -1e30f, mx1 = -1e30f;
    #pragma unroll
    for (int nt = 0; nt < 8; nt++) {
      mx0 = fmaxf(mx0, fmaxf(S[nt][0], S[nt][1]));
      mx1 = fmaxf(mx1, fmaxf(S[nt][2], S[nt][3]));
    }
    mx0 = fmaxf(mx0, __shfl_xor_sync(0xffffffffu, mx0, 1));
    mx0 = fmaxf(mx0, __shfl_xor_sync(0xffffffffu, mx0, 2));
    mx1 = fmaxf(mx1, __shfl_xor_sync(0xffffffffu, mx1, 1));
    mx1 = fmaxf(mx1, __shfl_xor_sync(0xffffffffu, mx1, 2));
    const float mn0 = fmaxf(m0r, mx0), mn1 = fmaxf(m1r, mx1);
    const float al0 = __expf(m0r - mn0), al1 = __expf(m1r - mn1);
    m0r = mn0; m1r = mn1;
    float ls0 = 0.f, ls1 = 0.f;
    #pragma unroll
    for (int nt = 0; nt < 8; nt++) {
      S[nt][0] = __expf(S[nt][0] - mn0); ls0 += S[nt][0];
      S[nt][1] = __expf(S[nt][1] - mn0); ls0 += S[nt][1];
      S[nt][2] = __expf(S[nt][2] - mn1); ls1 += S[nt][2];
      S[nt][3] = __expf(S[nt][3] - mn1); ls1 += S[nt][3];
    }
    ls0 += __shfl_xor_sync(0xffffffffu, ls0, 1);
    ls0 += __shfl_xor_sync(0xffffffffu, ls0, 2);
    ls1 += __shfl_xor_sync(0xffffffffu, ls1, 1);
    ls1 += __shfl_xor_sync(0xffffffffu, ls1, 2);
    l0r = l0r * al0 + ls0;
    l1r = l1r * al1 + ls1;
    #pragma unroll
    for (int nt = 0; nt < 8; nt++) {
      O[nt][0] *= al0; O[nt][1] *= al0;
      O[nt][2] *= al1; O[nt][3] *= al1;
    }

    // O += P V (single pass)
    #pragma unroll
    for (int kc = 0; kc < 4; kc++) {
      const uint32_t a0 = pack2(S[2*kc][0],   S[2*kc][1]);
      const uint32_t a1 = pack2(S[2*kc][2],   S[2*kc][3]);
      const uint32_t a2 = pack2(S[2*kc+1][0], S[2*kc+1][1]);
      const uint32_t a3 = pack2(S[2*kc+1][2], S[2*kc+1][3]);
      const int kc16 = kc * 16;
      #pragma unroll
      for (int np = 0; np < 4; np++) {
        uint32_t vh[4];
        const uint32_t voff = (uint32_t)(((np * 16 + b_row) * 72 + kc16 + b_col) * 2);
        ldsm4(tVh + voff, vh);
        #pragma unroll
        for (int j = 0; j < 2; j++) {
          const int nd = np * 2 + j;
          mma_f16(O[nd], a0, a1, a2, a3, vh[2*j], vh[2*j+1]);
        }
      }
    }
    if (jb + 1 < nb) { cp_wait<0>(); __syncthreads(); }
  }

  // epilogue
  const float inv0 = 1.f / l0r, inv1 = 1.f / l1r;
  const int colb = (bh & 15) * DH;
  const size_t orow0 = (size_t)(bh >> 4) * TT + row0g;
  const size_t orow1 = orow0 + 8;
  #pragma unroll
  for (int nd = 0; nd < 8; nd++) {
    const int d0 = nd * 8 + 2 * q;
    __half2* p0 = (__half2*)&g_Ah[orow0 * EE + colb + d0];
    __half2* p1 = (__half2*)&g_Ah[orow1 * EE + colb + d0];
    *p0 = __floats2half2_rn(O[nd][0] * inv0, O[nd][1] * inv0);
    *p1 = __floats2half2_rn(O[nd][2] * inv1, O[nd][3] * inv1);
  }
}

// ---------------------------------------------------------------------------
extern "C" void kernel_launch(void* const* d_in, const int* in_sizes, int n_in,
                              void* d_out, int out_size) {
  const float* x  = (const float*)d_in[0];
  const float* Wq = (const float*)d_in[1];
  const float* Wk = (const float*)d_in[2];
  const float* Wv = (const float*)d_in[3];
  const float* Wo = (const float*)d_in[4];
  const float* wb = (const float*)d_in[5];
  float* out = (float*)d_out;

  __half *xh, *wth, *wtl, *woh, *ah;
  cudaGetSymbolAddress((void**)&xh, g_xh);
  cudaGetSymbolAddress((void**)&wth, g_Wth); cudaGetSymbolAddress((void**)&wtl, g_Wtl);
  cudaGetSymbolAddress((void**)&woh, g_Woh);
  cudaGetSymbolAddress((void**)&ah, g_Ah);

  cudaFuncSetAttribute(gemm_f16<0,1>, cudaFuncAttributeMaxDynamicSharedMemorySize, GEMM_SMEM_SPLIT);
  cudaFuncSetAttribute(gemm_f16<1,0>, cudaFuncAttributeMaxDynamicSharedMemorySize, GEMM_SMEM_PLAIN);
  cudaFuncSetAttribute(attn_f16, cudaFuncAttributeMaxDynamicSharedMemorySize, ATT_SMEM);

  conv_h<<<(MTOT*EE/4 + 255)/256, 256>>>(x, xh, MTOT*EE/4);
  conv_h<<<(EE*EE/4 + 255)/256, 256>>>(Wo, woh, EE*EE/4);
  transpose_w<<<dim3(EE/32, DH/32, 48), dim3(32, 8)>>>(Wq, Wk, Wv);

  gemm_f16<0,1><<<dim3(3*EE/128, MTOT/128), 256, GEMM_SMEM_SPLIT>>>(xh, wth, wtl, nullptr, nullptr);

  attn_f16<<<dim3(TT/128, BHN), 256, ATT_SMEM>>>();

  gemm_f16<1,0><<<dim3(EE/128, MTOT/128), 256, GEMM_SMEM_PLAIN>>>(ah, woh, nullptr, wb, out);
}

// round 10
// speedup vs baseline: 5.1666x; 1.1837x over previous
#include <cuda_runtime.h>
#include <cuda_fp16.h>
#include <cstdint>

#define BB 2
#define TT 2048
#define EE 1024
#define HH 16
#define DH 64
#define MTOT (BB*TT)   // 4096
#define BHN (BB*HH)    // 32

// ---------------------------------------------------------------------------
// Global scratch. Only K keeps hi/lo split (exp-sensitive); rest fp16-rounded.
// ---------------------------------------------------------------------------
__device__ __align__(128) __half g_xh[(size_t)MTOT*EE];
__device__ __align__(128) __half g_Wth[(size_t)3*EE*EE];   // [3072][1024]
__device__ __align__(128) __half g_Qh[(size_t)BHN*TT*DH];  // [bh][t][d] (x0.125)
__device__ __align__(128) __half g_Kh[(size_t)BHN*TT*DH];  // [bh][t][d]
__device__ __align__(128) __half g_Kl[(size_t)BHN*TT*DH];
__device__ __align__(128) __half g_Vt[(size_t)BHN*TT*DH];  // [bh][d][t]
__device__ __align__(128) __half g_Ah[(size_t)MTOT*EE];    // attn out
__device__ __align__(128) __half g_Woh[(size_t)EE*EE];     // [out][in]

// ---------------------------------------------------------------------------
// Helpers
// ---------------------------------------------------------------------------
__device__ __forceinline__ uint32_t smem_u32(const void* p) {
  uint32_t a;
  asm("{ .reg .u64 t; cvta.to.shared.u64 t, %1; cvt.u32.u64 %0, t; }" : "=r"(a) : "l"(p));
  return a;
}
__device__ __forceinline__ void ldsm4(uint32_t addr, uint32_t r[4]) {
  asm volatile("ldmatrix.sync.aligned.m8n8.x4.shared.b16 {%0,%1,%2,%3}, [%4];"
               : "=r"(r[0]), "=r"(r[1]), "=r"(r[2]), "=r"(r[3]) : "r"(addr));
}
__device__ __forceinline__ void cp16(uint32_t dst, const void* src) {
  asm volatile("cp.async.ca.shared.global [%0], [%1], 16;" :: "r"(dst), "l"(src) : "memory");
}
__device__ __forceinline__ void cp_commit() {
  asm volatile("cp.async.commit_group;" ::: "memory");
}
template<int N> __device__ __forceinline__ void cp_wait() {
  asm volatile("cp.async.wait_group %0;" :: "n"(N) : "memory");
}
__device__ __forceinline__ void f16_split(float x, __half& h, __half& l) {
  h = __float2half_rn(x);
  l = __float2half_rn(x - __half2float(h));
}
__device__ __forceinline__ void store_split(__half* H, __half* L, size_t idx, float v) {
  __half h, l; f16_split(v, h, l);
  H[idx] = h; L[idx] = l;
}
__device__ __forceinline__ uint32_t pack2(float a, float b) {  // a -> low half
  __half2 h = __floats2half2_rn(a, b);
  return *(uint32_t*)&h;
}
__device__ __forceinline__ void mma_f16(float c[4], uint32_t a0, uint32_t a1,
                                        uint32_t a2, uint32_t a3,
                                        uint32_t b0, uint32_t b1) {
  asm volatile(
    "mma.sync.aligned.m16n8k16.row.col.f32.f16.f16.f32 "
    "{%0,%1,%2,%3},{%4,%5,%6,%7},{%8,%9},{%0,%1,%2,%3};"
    : "+f"(c[0]), "+f"(c[1]), "+f"(c[2]), "+f"(c[3])
    : "r"(a0), "r"(a1), "r"(a2), "r"(a3), "r"(b0), "r"(b1));
}

// ---------------------------------------------------------------------------
// Conversions
// ---------------------------------------------------------------------------
__global__ __launch_bounds__(256) void conv_h(const float* __restrict__ s,
                                              __half* __restrict__ H, int n4) {
  int i = blockIdx.x * 256 + threadIdx.x;
  if (i >= n4) return;
  float4 v = ((const float4*)s)[i];
  __half2* Hp = (__half2*)(H + (size_t)i*4);
  Hp[0] = __floats2half2_rn(v.x, v.y);
  Hp[1] = __floats2half2_rn(v.z, v.w);
}

// ---------------------------------------------------------------------------
// Weight transpose (QKV, hi only): g_Wth[(p*16+h)*64 + d][e] = W_p[h][e][d]
// ---------------------------------------------------------------------------
__global__ __launch_bounds__(256) void transpose_w(
    const float* __restrict__ Wq, const float* __restrict__ Wk,
    const float* __restrict__ Wv) {
  __shared__ float t[32][33];
  const int bz = blockIdx.z;
  const int p = bz >> 4;
  const float* W = (p == 0 ? Wq : p == 1 ? Wk : Wv) + (size_t)(bz & 15) * EE * DH;
  const int e0 = blockIdx.x * 32;
  const int d0 = blockIdx.y * 32;
  const int tx = threadIdx.x, ty = threadIdx.y;
  #pragma unroll
  for (int i = ty; i < 32; i += 8)
    t[i][tx] = W[(size_t)(e0 + i) * DH + d0 + tx];
  __syncthreads();
  #pragma unroll
  for (int i = ty; i < 32; i += 8)
    g_Wth[(size_t)(bz * DH + d0 + i) * EE + e0 + tx] = __float2half_rn(t[tx][i]);
}

// ---------------------------------------------------------------------------
// fp16 GEMM, single-pass operands. BM=128 BN=128 BK=32, 256 thr,
// 4-stage cp.async pipeline, one barrier per k-iter, ldmatrix frags.
// ---------------------------------------------------------------------------
#define NKIT (EE / 32)                // 32
#define G_TILE_H 5120                 // halves per 128x40 tile
#define G_STAGE_B (2 * G_TILE_H * 2)  // 20480 bytes (A,B)
#define GEMM_SMEM (4 * G_STAGE_B)     // 81920

template<int MODE>
__global__ __launch_bounds__(256, 2) void gemm_f16(
    const __half* __restrict__ pAh, const __half* __restrict__ pBh,
    const float* __restrict__ bias, float* __restrict__ outp) {
  extern __shared__ __align__(16) char gsm[];
  const int tid = threadIdx.x;
  const int lane = tid & 31, q = lane & 3, g = lane >> 2;
  const int wid = tid >> 5, wm = wid >> 2, wn = wid & 3;
  const int n0 = blockIdx.x * 128;
  const size_t m0 = (size_t)blockIdx.y * 128;
  const uint32_t s0 = smem_u32(gsm);

  const int a_row = lane & 15;
  const int a_col = (lane >> 4) << 3;
  const int b_row = (lane & 7) + ((lane >> 4) << 3);
  const int b_col = ((lane >> 3) & 1) << 3;

  float C[4][4][4];
  #pragma unroll
  for (int a = 0; a < 4; a++)
    #pragma unroll
    for (int b = 0; b < 4; b++)
      #pragma unroll
      for (int c = 0; c < 4; c++) C[a][b][c] = 0.f;

  auto issue = [&](int stage, int k0) {
    const uint32_t sb = s0 + (uint32_t)stage * G_STAGE_B;
    #pragma unroll
    for (int t = 0; t < 4; t++) {
      int c = tid + t * 256;
      int arr = c >> 9, rem = c & 511;
      int row = rem >> 2, seg = rem & 3;
      const __half* src = arr ? pBh + (size_t)(n0 + row) * EE + k0 + seg * 8
                              : pAh + (m0 + row) * EE + k0 + seg * 8;
      cp16(sb + (uint32_t)(arr * G_TILE_H + row * 40 + seg * 8) * 2, src);
    }
    cp_commit();
  };

  issue(0, 0);
  issue(1, 32);
  issue(2, 64);
  cp_wait<2>(); __syncthreads();

  for (int i = 0; i < NKIT; i++) {
    if (i + 3 < NKIT) issue((i + 3) & 3, (i + 3) * 32);
    const uint32_t sb = s0 + (uint32_t)(i & 3) * G_STAGE_B;
    const uint32_t tAh = sb, tBh = sb + G_TILE_H*2;
    #pragma unroll
    for (int kc = 0; kc < 2; kc++) {
      const int kc16 = kc * 16;
      uint32_t ah[4][4];
      #pragma unroll
      for (int mt = 0; mt < 4; mt++) {
        const uint32_t off = (uint32_t)(((wm * 64 + mt * 16 + a_row) * 40 + kc16 + a_col) * 2);
        ldsm4(tAh + off, ah[mt]);
      }
      uint32_t bhf[2][4];
      #pragma unroll
      for (int np = 0; np < 2; np++) {
        const uint32_t off = (uint32_t)(((wn * 32 + np * 16 + b_row) * 40 + kc16 + b_col) * 2);
        ldsm4(tBh + off, bhf[np]);
      }
      #pragma unroll
      for (int np = 0; np < 2; np++) {
        #pragma unroll
        for (int j = 0; j < 2; j++) {
          const int nt = np * 2 + j;
          #pragma unroll
          for (int mt = 0; mt < 4; mt++)
            mma_f16(C[mt][nt], ah[mt][0], ah[mt][1], ah[mt][2], ah[mt][3],
                    bhf[np][2*j], bhf[np][2*j+1]);
        }
      }
    }
    if (i + 1 < NKIT) {
      if (i + 3 < NKIT)      cp_wait<2>();
      else if (i + 2 < NKIT) cp_wait<1>();
      else                   cp_wait<0>();
      __syncthreads();
    }
  }

  // epilogue
  #pragma unroll
  for (int mt = 0; mt < 4; mt++) {
    #pragma unroll
    for (int nt = 0; nt < 4; nt++) {
      #pragma unroll
      for (int e = 0; e < 4; e++) {
        const int r = (int)m0 + wm * 64 + mt * 16 + g + (e >= 2 ? 8 : 0);
        const int c = n0 + wn * 32 + nt * 8 + 2 * q + (e & 1);
        const float v = C[mt][nt][e];
        if (MODE == 0) {
          const int p = c >> 10, rl = c & 1023, hh = rl >> 6, d = rl & 63;
          const int bhi = (r >> 11) * HH + hh, t = r & (TT - 1);
          if (p == 2) {
            g_Vt[((size_t)bhi * DH + d) * TT + t] = __float2half_rn(v);
          } else if (p == 1) {
            store_split(g_Kh, g_Kl, ((size_t)bhi * TT + t) * DH + d, v);
          } else {
            g_Qh[((size_t)bhi * TT + t) * DH + d] = __float2half_rn(v * 0.125f);
          }
        } else {
          outp[(size_t)r * EE + c] = v + bias[c];
        }
      }
    }
  }
}

// ---------------------------------------------------------------------------
// fp16 flash attention: QK 2-pass (K split), PV single pass (V rounded).
// Q pre-scaled by 0.125. One barrier per KV block.
// ---------------------------------------------------------------------------
#define AT_Q_H   9216       // 128*72
#define AT_T_H   4608       // 64*72
#define AT_KV_H  (3 * AT_T_H)
#define ATT_SMEM ((AT_Q_H + 2 * AT_KV_H) * 2)   // 73728 bytes

__global__ __launch_bounds__(256, 2) void attn_f16() {
  extern __shared__ __align__(16) char asm_[];
  const int tid = threadIdx.x;
  const int lane = tid & 31, q = lane & 3, g = lane >> 2;
  const int wid = tid >> 5;
  const int i0 = ((int)gridDim.x - 1 - (int)blockIdx.x) * 128;  // heavy CTAs first
  const int bh = blockIdx.y;
  const uint32_t s0 = smem_u32(asm_);
  const uint32_t pQh = s0;
  const uint32_t kvBase = s0 + AT_Q_H * 2;

  const int a_row = lane & 15;
  const int a_col = (lane >> 4) << 3;
  const int b_row = (lane & 7) + ((lane >> 4) << 3);
  const int b_col = ((lane >> 3) & 1) << 3;

  // Q (hi only)
  #pragma unroll
  for (int t = 0; t < 4; t++) {
    int c = tid + t * 256;
    int row = c >> 3, seg = c & 7;
    const __half* src = g_Qh + ((size_t)bh * TT + i0 + row) * DH + seg * 8;
    cp16(pQh + (uint32_t)(row * 72 + seg * 8) * 2, src);
  }
  auto issue_kv = [&](int stage, int j0) {
    const uint32_t kb = kvBase + (uint32_t)stage * AT_KV_H * 2;
    #pragma unroll
    for (int t = 0; t < 6; t++) {
      int c = tid + t * 256;
      int arr = c >> 9, rem = c & 511, row = rem >> 3, seg = rem & 7;
      const __half* src;
      if (arr == 0)      src = g_Kh + ((size_t)bh * TT + j0 + row) * DH + seg * 8;
      else if (arr == 1) src = g_Kl + ((size_t)bh * TT + j0 + row) * DH + seg * 8;
      else               src = g_Vt + ((size_t)bh * DH + row) * TT + j0 + seg * 8;
      cp16(kb + (uint32_t)(arr * AT_T_H + row * 72 + seg * 8) * 2, src);
    }
    cp_commit();
  };

  const int nb = i0 / 64 + 2;
  issue_kv(0, 0);
  cp_wait<0>(); __syncthreads();

  float O[8][4];
  #pragma unroll
  for (int a = 0; a < 8; a++)
    #pragma unroll
    for (int e = 0; e < 4; e++) O[a][e] = 0.f;
  float m0r = -1e30f, m1r = -1e30f, l0r = 0.f, l1r = 0.f;
  const int row0g = i0 + wid * 16 + g;
  const int row1g = row0g + 8;

  for (int jb = 0; jb < nb; jb++) {
    if (jb + 1 < nb) issue_kv((jb + 1) & 1, (jb + 1) * 64);
    const uint32_t kb = kvBase + (uint32_t)(jb & 1) * AT_KV_H * 2;
    const uint32_t tKh = kb, tKl = kb + AT_T_H*2, tVh = kb + 2*AT_T_H*2;

    // S = Q K^T (Q rounded+prescaled, K split)
    float S[8][4];
    #pragma unroll
    for (int a = 0; a < 8; a++)
      #pragma unroll
      for (int e = 0; e < 4; e++) S[a][e] = 0.f;
    #pragma unroll
    for (int kc = 0; kc < 4; kc++) {
      const int kc16 = kc * 16;
      uint32_t qh[4];
      const uint32_t qoff = (uint32_t)(((wid * 16 + a_row) * 72 + kc16 + a_col) * 2);
      ldsm4(pQh + qoff, qh);
      #pragma unroll
      for (int np = 0; np < 4; np++) {
        uint32_t kh[4], kl[4];
        const uint32_t koff = (uint32_t)(((np * 16 + b_row) * 72 + kc16 + b_col) * 2);
        ldsm4(tKh + koff, kh);
        ldsm4(tKl + koff, kl);
        #pragma unroll
        for (int j = 0; j < 2; j++) {
          const int nt = np * 2 + j;
          mma_f16(S[nt], qh[0], qh[1], qh[2], qh[3], kh[2*j], kh[2*j+1]);
          mma_f16(S[nt], qh[0], qh[1], qh[2], qh[3], kl[2*j], kl[2*j+1]);
        }
      }
    }

    // causal mask (scale folded into Q)
    const int j0 = jb * 64;
    if (j0 >= i0) {
      #pragma unroll
      for (int nt = 0; nt < 8; nt++) {
        const int cb = j0 + nt * 8 + 2 * q;
        if (cb     > row0g) S[nt][0] = -1e30f;
        if (cb + 1 > row0g) S[nt][1] = -1e30f;
        if (cb     > row1g) S[nt][2] = -1e30f;
        if (cb + 1 > row1g) S[nt][3] = -1e30f;
      }
    }

    // online softmax
    float mx0 = -1e30f, mx1 = -1e30f;
    #pragma unroll
    for (int nt = 0; nt < 8; nt++) {
      mx0 = fmaxf(mx0, fmaxf(S[nt][0], S[nt][1]));
      mx1 = fmaxf(mx1, fmaxf(S[nt][2], S[nt][3]));
    }
    mx0 = fmaxf(mx0, __shfl_xor_sync(0xffffffffu, mx0, 1));
    mx0 = fmaxf(mx0, __shfl_xor_sync(0xffffffffu, mx0, 2));
    mx1 = fmaxf(mx1, __shfl_xor_sync(0xffffffffu, mx1, 1));
    mx1 = fmaxf(mx1, __shfl_xor_sync(0xffffffffu, mx1, 2));
    const float mn0 = fmaxf(m0r, mx0), mn1 = fmaxf(m1r, mx1);
    const float al0 = __expf(m0r - mn0), al1 = __expf(m1r - mn1);
    m0r = mn0; m1r = mn1;
    float ls0 = 0.f, ls1 = 0.f;
    #pragma unroll
    for (int nt = 0; nt < 8; nt++) {
      S[nt][0] = __expf(S[nt][0] - mn0); ls0 += S[nt][0];
      S[nt][1] = __expf(S[nt][1] - mn0); ls0 += S[nt][1];
      S[nt][2] = __expf(S[nt][2] - mn1); ls1 += S[nt][2];
      S[nt][3] = __expf(S[nt][3] - mn1); ls1 += S[nt][3];
    }
    ls0 += __shfl_xor_sync(0xffffffffu, ls0, 1);
    ls0 += __shfl_xor_sync(0xffffffffu, ls0, 2);
    ls1 += __shfl_xor_sync(0xffffffffu, ls1, 1);
    ls1 += __shfl_xor_sync(0xffffffffu, ls1, 2);
    l0r = l0r * al0 + ls0;
    l1r = l1r * al1 + ls1;
    #pragma unroll
    for (int nt = 0; nt < 8; nt++) {
      O[nt][0] *= al0; O[nt][1] *= al0;
      O[nt][2] *= al1; O[nt][3] *= al1;
    }

    // O += P V (single pass)
    #pragma unroll
    for (int kc = 0; kc < 4; kc++) {
      const uint32_t a0 = pack2(S[2*kc][0],   S[2*kc][1]);
      const uint32_t a1 = pack2(S[2*kc][2],   S[2*kc][3]);
      const uint32_t a2 = pack2(S[2*kc+1][0], S[2*kc+1][1]);
      const uint32_t a3 = pack2(S[2*kc+1][2], S[2*kc+1][3]);
      const int kc16 = kc * 16;
      #pragma unroll
      for (int np = 0; np < 4; np++) {
        uint32_t vh[4];
        const uint32_t voff = (uint32_t)(((np * 16 + b_row) * 72 + kc16 + b_col) * 2);
        ldsm4(tVh + voff, vh);
        #pragma unroll
        for (int j = 0; j < 2; j++) {
          const int nd = np * 2 + j;
          mma_f16(O[nd], a0, a1, a2, a3, vh[2*j], vh[2*j+1]);
        }
      }
    }
    if (jb + 1 < nb) { cp_wait<0>(); __syncthreads(); }
  }

  // epilogue
  const float inv0 = 1.f / l0r, inv1 = 1.f / l1r;
  const int colb = (bh & 15) * DH;
  const size_t orow0 = (size_t)(bh >> 4) * TT + row0g;
  const size_t orow1 = orow0 + 8;
  #pragma unroll
  for (int nd = 0; nd < 8; nd++) {
    const int d0 = nd * 8 + 2 * q;
    __half2* p0 = (__half2*)&g_Ah[orow0 * EE + colb + d0];
    __half2* p1 = (__half2*)&g_Ah[orow1 * EE + colb + d0];
    *p0 = __floats2half2_rn(O[nd][0] * inv0, O[nd][1] * inv0);
    *p1 = __floats2half2_rn(O[nd][2] * inv1, O[nd][3] * inv1);
  }
}

// ---------------------------------------------------------------------------
extern "C" void kernel_launch(void* const* d_in, const int* in_sizes, int n_in,
                              void* d_out, int out_size) {
  const float* x  = (const float*)d_in[0];
  const float* Wq = (const float*)d_in[1];
  const float* Wk = (const float*)d_in[2];
  const float* Wv = (const float*)d_in[3];
  const float* Wo = (const float*)d_in[4];
  const float* wb = (const float*)d_in[5];
  float* out = (float*)d_out;

  __half *xh, *wth, *woh, *ah;
  cudaGetSymbolAddress((void**)&xh, g_xh);
  cudaGetSymbolAddress((void**)&wth, g_Wth);
  cudaGetSymbolAddress((void**)&woh, g_Woh);
  cudaGetSymbolAddress((void**)&ah, g_Ah);

  cudaFuncSetAttribute(gemm_f16<0>, cudaFuncAttributeMaxDynamicSharedMemorySize, GEMM_SMEM);
  cudaFuncSetAttribute(gemm_f16<1>, cudaFuncAttributeMaxDynamicSharedMemorySize, GEMM_SMEM);
  cudaFuncSetAttribute(attn_f16, cudaFuncAttributeMaxDynamicSharedMemorySize, ATT_SMEM);

  conv_h<<<(MTOT*EE/4 + 255)/256, 256>>>(x, xh, MTOT*EE/4);
  conv_h<<<(EE*EE/4 + 255)/256, 256>>>(Wo, woh, EE*EE/4);
  transpose_w<<<dim3(EE/32, DH/32, 48), dim3(32, 8)>>>(Wq, Wk, Wv);

  gemm_f16<0><<<dim3(3*EE/128, MTOT/128), 256, GEMM_SMEM>>>(xh, wth, nullptr, nullptr);

  attn_f16<<<dim3(TT/128, BHN), 256, ATT_SMEM>>>();

  gemm_f16<1><<<dim3(EE/128, MTOT/128), 256, GEMM_SMEM>>>(ah, woh, wb, out);
}

// round 11
// speedup vs baseline: 6.0241x; 1.1660x over previous
#include <cuda_runtime.h>
#include <cuda_fp16.h>
#include <cstdint>

#define BB 2
#define TT 2048
#define EE 1024
#define HH 16
#define DH 64
#define MTOT (BB*TT)   // 4096
#define BHN (BB*HH)    // 32

// ---------------------------------------------------------------------------
// Global scratch. All operands fp16-rounded (error model calibrated R5-R10).
// ---------------------------------------------------------------------------
__device__ __align__(128) __half g_xh[(size_t)MTOT*EE];
__device__ __align__(128) __half g_Wth[(size_t)3*EE*EE];   // [3072][1024]
__device__ __align__(128) __half g_Qh[(size_t)BHN*TT*DH];  // [bh][t][d] (x0.125)
__device__ __align__(128) __half g_Kh[(size_t)BHN*TT*DH];  // [bh][t][d]
__device__ __align__(128) __half g_Vt[(size_t)BHN*TT*DH];  // [bh][d][t]
__device__ __align__(128) __half g_Ah[(size_t)MTOT*EE];    // attn out
__device__ __align__(128) __half g_Woh[(size_t)EE*EE];     // [out][in]

// ---------------------------------------------------------------------------
// Helpers
// ---------------------------------------------------------------------------
__device__ __forceinline__ uint32_t smem_u32(const void* p) {
  uint32_t a;
  asm("{ .reg .u64 t; cvta.to.shared.u64 t, %1; cvt.u32.u64 %0, t; }" : "=r"(a) : "l"(p));
  return a;
}
__device__ __forceinline__ void ldsm4(uint32_t addr, uint32_t r[4]) {
  asm volatile("ldmatrix.sync.aligned.m8n8.x4.shared.b16 {%0,%1,%2,%3}, [%4];"
               : "=r"(r[0]), "=r"(r[1]), "=r"(r[2]), "=r"(r[3]) : "r"(addr));
}
__device__ __forceinline__ void cp16(uint32_t dst, const void* src) {
  asm volatile("cp.async.ca.shared.global [%0], [%1], 16;" :: "r"(dst), "l"(src) : "memory");
}
__device__ __forceinline__ void cp_commit() {
  asm volatile("cp.async.commit_group;" ::: "memory");
}
template<int N> __device__ __forceinline__ void cp_wait() {
  asm volatile("cp.async.wait_group %0;" :: "n"(N) : "memory");
}
__device__ __forceinline__ uint32_t pack2(float a, float b) {  // a -> low half
  __half2 h = __floats2half2_rn(a, b);
  return *(uint32_t*)&h;
}
__device__ __forceinline__ void mma_f16(float c[4], uint32_t a0, uint32_t a1,
                                        uint32_t a2, uint32_t a3,
                                        uint32_t b0, uint32_t b1) {
  asm volatile(
    "mma.sync.aligned.m16n8k16.row.col.f32.f16.f16.f32 "
    "{%0,%1,%2,%3},{%4,%5,%6,%7},{%8,%9},{%0,%1,%2,%3};"
    : "+f"(c[0]), "+f"(c[1]), "+f"(c[2]), "+f"(c[3])
    : "r"(a0), "r"(a1), "r"(a2), "r"(a3), "r"(b0), "r"(b1));
}

// ---------------------------------------------------------------------------
// Conversions
// ---------------------------------------------------------------------------
__global__ __launch_bounds__(256) void conv_h(const float* __restrict__ s,
                                              __half* __restrict__ H, int n4) {
  int i = blockIdx.x * 256 + threadIdx.x;
  if (i >= n4) return;
  float4 v = ((const float4*)s)[i];
  __half2* Hp = (__half2*)(H + (size_t)i*4);
  Hp[0] = __floats2half2_rn(v.x, v.y);
  Hp[1] = __floats2half2_rn(v.z, v.w);
}

// ---------------------------------------------------------------------------
// Weight transpose (QKV): g_Wth[(p*16+h)*64 + d][e] = W_p[h][e][d]
// ---------------------------------------------------------------------------
__global__ __launch_bounds__(256) void transpose_w(
    const float* __restrict__ Wq, const float* __restrict__ Wk,
    const float* __restrict__ Wv) {
  __shared__ float t[32][33];
  const int bz = blockIdx.z;
  const int p = bz >> 4;
  const float* W = (p == 0 ? Wq : p == 1 ? Wk : Wv) + (size_t)(bz & 15) * EE * DH;
  const int e0 = blockIdx.x * 32;
  const int d0 = blockIdx.y * 32;
  const int tx = threadIdx.x, ty = threadIdx.y;
  #pragma unroll
  for (int i = ty; i < 32; i += 8)
    t[i][tx] = W[(size_t)(e0 + i) * DH + d0 + tx];
  __syncthreads();
  #pragma unroll
  for (int i = ty; i < 32; i += 8)
    g_Wth[(size_t)(bz * DH + d0 + i) * EE + e0 + tx] = __float2half_rn(t[tx][i]);
}

// ---------------------------------------------------------------------------
// fp16 GEMM. BM=128 BN=128 BK=32, 256 thr, 4-stage cp.async, ldmatrix frags.
// ---------------------------------------------------------------------------
#define NKIT (EE / 32)                // 32
#define G_TILE_H 5120                 // halves per 128x40 tile
#define G_STAGE_B (2 * G_TILE_H * 2)  // 20480 bytes (A,B)
#define GEMM_SMEM (4 * G_STAGE_B)     // 81920

template<int MODE>
__global__ __launch_bounds__(256, 2) void gemm_f16(
    const __half* __restrict__ pAh, const __half* __restrict__ pBh,
    const float* __restrict__ bias, float* __restrict__ outp) {
  extern __shared__ __align__(16) char gsm[];
  const int tid = threadIdx.x;
  const int lane = tid & 31, q = lane & 3, g = lane >> 2;
  const int wid = tid >> 5, wm = wid >> 2, wn = wid & 3;
  const int n0 = blockIdx.x * 128;
  const size_t m0 = (size_t)blockIdx.y * 128;
  const uint32_t s0 = smem_u32(gsm);

  const int a_row = lane & 15;
  const int a_col = (lane >> 4) << 3;
  const int b_row = (lane & 7) + ((lane >> 4) << 3);
  const int b_col = ((lane >> 3) & 1) << 3;

  float C[4][4][4];
  #pragma unroll
  for (int a = 0; a < 4; a++)
    #pragma unroll
    for (int b = 0; b < 4; b++)
      #pragma unroll
      for (int c = 0; c < 4; c++) C[a][b][c] = 0.f;

  auto issue = [&](int stage, int k0) {
    const uint32_t sb = s0 + (uint32_t)stage * G_STAGE_B;
    #pragma unroll
    for (int t = 0; t < 4; t++) {
      int c = tid + t * 256;
      int arr = c >> 9, rem = c & 511;
      int row = rem >> 2, seg = rem & 3;
      const __half* src = arr ? pBh + (size_t)(n0 + row) * EE + k0 + seg * 8
                              : pAh + (m0 + row) * EE + k0 + seg * 8;
      cp16(sb + (uint32_t)(arr * G_TILE_H + row * 40 + seg * 8) * 2, src);
    }
    cp_commit();
  };

  issue(0, 0);
  issue(1, 32);
  issue(2, 64);
  cp_wait<2>(); __syncthreads();

  for (int i = 0; i < NKIT; i++) {
    if (i + 3 < NKIT) issue((i + 3) & 3, (i + 3) * 32);
    const uint32_t sb = s0 + (uint32_t)(i & 3) * G_STAGE_B;
    const uint32_t tAh = sb, tBh = sb + G_TILE_H*2;
    #pragma unroll
    for (int kc = 0; kc < 2; kc++) {
      const int kc16 = kc * 16;
      uint32_t ah[4][4];
      #pragma unroll
      for (int mt = 0; mt < 4; mt++) {
        const uint32_t off = (uint32_t)(((wm * 64 + mt * 16 + a_row) * 40 + kc16 + a_col) * 2);
        ldsm4(tAh + off, ah[mt]);
      }
      uint32_t bhf[2][4];
      #pragma unroll
      for (int np = 0; np < 2; np++) {
        const uint32_t off = (uint32_t)(((wn * 32 + np * 16 + b_row) * 40 + kc16 + b_col) * 2);
        ldsm4(tBh + off, bhf[np]);
      }
      #pragma unroll
      for (int np = 0; np < 2; np++) {
        #pragma unroll
        for (int j = 0; j < 2; j++) {
          const int nt = np * 2 + j;
          #pragma unroll
          for (int mt = 0; mt < 4; mt++)
            mma_f16(C[mt][nt], ah[mt][0], ah[mt][1], ah[mt][2], ah[mt][3],
                    bhf[np][2*j], bhf[np][2*j+1]);
        }
      }
    }
    if (i + 1 < NKIT) {
      if (i + 3 < NKIT)      cp_wait<2>();
      else if (i + 2 < NKIT) cp_wait<1>();
      else                   cp_wait<0>();
      __syncthreads();
    }
  }

  // epilogue
  #pragma unroll
  for (int mt = 0; mt < 4; mt++) {
    #pragma unroll
    for (int nt = 0; nt < 4; nt++) {
      #pragma unroll
      for (int e = 0; e < 4; e++) {
        const int r = (int)m0 + wm * 64 + mt * 16 + g + (e >= 2 ? 8 : 0);
        const int c = n0 + wn * 32 + nt * 8 + 2 * q + (e & 1);
        const float v = C[mt][nt][e];
        if (MODE == 0) {
          const int p = c >> 10, rl = c & 1023, hh = rl >> 6, d = rl & 63;
          const int bhi = (r >> 11) * HH + hh, t = r & (TT - 1);
          if (p == 2) {
            g_Vt[((size_t)bhi * DH + d) * TT + t] = __float2half_rn(v);
          } else if (p == 1) {
            g_Kh[((size_t)bhi * TT + t) * DH + d] = __float2half_rn(v);
          } else {
            g_Qh[((size_t)bhi * TT + t) * DH + d] = __float2half_rn(v * 0.125f);
          }
        } else {
          outp[(size_t)r * EE + c] = v + bias[c];
        }
      }
    }
  }
}

// ---------------------------------------------------------------------------
// fp16 flash attention, single-pass QK and PV. Q pre-scaled by 0.125.
// 3-stage KV pipeline (2 blocks ahead), one barrier per KV block.
// ---------------------------------------------------------------------------
#define AT_Q_H   9216       // 128*72
#define AT_T_H   4608       // 64*72
#define AT_KV_H  (2 * AT_T_H)                    // Kh + Vt
#define ATT_SMEM ((AT_Q_H + 3 * AT_KV_H) * 2)    // 73728 bytes

__global__ __launch_bounds__(256, 2) void attn_f16() {
  extern __shared__ __align__(16) char asm_[];
  const int tid = threadIdx.x;
  const int lane = tid & 31, q = lane & 3, g = lane >> 2;
  const int wid = tid >> 5;
  const int i0 = ((int)gridDim.x - 1 - (int)blockIdx.x) * 128;  // heavy CTAs first
  const int bh = blockIdx.y;
  const uint32_t s0 = smem_u32(asm_);
  const uint32_t pQh = s0;
  const uint32_t kvBase = s0 + AT_Q_H * 2;

  const int a_row = lane & 15;
  const int a_col = (lane >> 4) << 3;
  const int b_row = (lane & 7) + ((lane >> 4) << 3);
  const int b_col = ((lane >> 3) & 1) << 3;

  // Q (joins KV group 0)
  #pragma unroll
  for (int t = 0; t < 4; t++) {
    int c = tid + t * 256;
    int row = c >> 3, seg = c & 7;
    const __half* src = g_Qh + ((size_t)bh * TT + i0 + row) * DH + seg * 8;
    cp16(pQh + (uint32_t)(row * 72 + seg * 8) * 2, src);
  }
  auto issue_kv = [&](int stage, int j0) {
    const uint32_t kb = kvBase + (uint32_t)stage * AT_KV_H * 2;
    #pragma unroll
    for (int t = 0; t < 4; t++) {
      int c = tid + t * 256;
      int arr = c >> 9, rem = c & 511, row = rem >> 3, seg = rem & 7;
      const __half* src = arr ? g_Vt + ((size_t)bh * DH + row) * TT + j0 + seg * 8
                              : g_Kh + ((size_t)bh * TT + j0 + row) * DH + seg * 8;
      cp16(kb + (uint32_t)(arr * AT_T_H + row * 72 + seg * 8) * 2, src);
    }
    cp_commit();
  };

  const int nb = i0 / 64 + 2;
  issue_kv(0, 0);
  if (nb > 1) { issue_kv(1, 64); cp_wait<1>(); }
  else        cp_wait<0>();
  __syncthreads();

  float O[8][4];
  #pragma unroll
  for (int a = 0; a < 8; a++)
    #pragma unroll
    for (int e = 0; e < 4; e++) O[a][e] = 0.f;
  float m0r = -1e30f, m1r = -1e30f, l0r = 0.f, l1r = 0.f;
  const int row0g = i0 + wid * 16 + g;
  const int row1g = row0g + 8;

  for (int jb = 0; jb < nb; jb++) {
    if (jb + 2 < nb) issue_kv((jb + 2) % 3, (jb + 2) * 64);
    const uint32_t kb = kvBase + (uint32_t)(jb % 3) * AT_KV_H * 2;
    const uint32_t tKh = kb, tVh = kb + AT_T_H*2;

    // S = Q K^T (single pass)
    float S[8][4];
    #pragma unroll
    for (int a = 0; a < 8; a++)
      #pragma unroll
      for (int e = 0; e < 4; e++) S[a][e] = 0.f;
    #pragma unroll
    for (int kc = 0; kc < 4; kc++) {
      const int kc16 = kc * 16;
      uint32_t qh[4];
      const uint32_t qoff = (uint32_t)(((wid * 16 + a_row) * 72 + kc16 + a_col) * 2);
      ldsm4(pQh + qoff, qh);
      #pragma unroll
      for (int np = 0; np < 4; np++) {
        uint32_t kh[4];
        const uint32_t koff = (uint32_t)(((np * 16 + b_row) * 72 + kc16 + b_col) * 2);
        ldsm4(tKh + koff, kh);
        #pragma unroll
        for (int j = 0; j < 2; j++)
          mma_f16(S[np * 2 + j], qh[0], qh[1], qh[2], qh[3], kh[2*j], kh[2*j+1]);
      }
    }

    // causal mask (scale folded into Q)
    const int j0 = jb * 64;
    if (j0 >= i0) {
      #pragma unroll
      for (int nt = 0; nt < 8; nt++) {
        const int cb = j0 + nt * 8 + 2 * q;
        if (cb     > row0g) S[nt][0] = -1e30f;
        if (cb + 1 > row0g) S[nt][1] = -1e30f;
        if (cb     > row1g) S[nt][2] = -1e30f;
        if (cb + 1 > row1g) S[nt][3] = -1e30f;
      }
    }

    // online softmax
    float mx0 = -1e30f, mx1 = -1e30f;
    #pragma unroll
    for (int nt = 0; nt < 8; nt++) {
      mx0 = fmaxf(mx0, fmaxf(S[nt][0], S[nt][1]));
      mx1 = fmaxf(mx1, fmaxf(S[nt][2], S[nt][3]));
    }
    mx0 = fmaxf(mx0, __shfl_xor_sync(0xffffffffu, mx0, 1));
    mx0 = fmaxf(mx0, __shfl_xor_sync(0xffffffffu, mx0, 2));
    mx1 = fmaxf(mx1, __shfl_xor_sync(0xffffffffu, mx1, 1));
    mx1 = fmaxf(mx1, __shfl_xor_sync(0xffffffffu, mx1, 2));
    const float mn0 = fmaxf(m0r, mx0), mn1 = fmaxf(m1r, mx1);
    const float al0 = __expf(m0r - mn0), al1 = __expf(m1r - mn1);
    m0r = mn0; m1r = mn1;
    float ls0 = 0.f, ls1 = 0.f;
    #pragma unroll
    for (int nt = 0; nt < 8; nt++) {
      S[nt][0] = __expf(S[nt][0] - mn0); ls0 += S[nt][0];
      S[nt][1] = __expf(S[nt][1] - mn0); ls0 += S[nt][1];
      S[nt][2] = __expf(S[nt][2] - mn1); ls1 += S[nt][2];
      S[nt][3] = __expf(S[nt][3] - mn1); ls1 += S[nt][3];
    }
    ls0 += __shfl_xor_sync(0xffffffffu, ls0, 1);
    ls0 += __shfl_xor_sync(0xffffffffu, ls0, 2);
    ls1 += __shfl_xor_sync(0xffffffffu, ls1, 1);
    ls1 += __shfl_xor_sync(0xffffffffu, ls1, 2);
    l0r = l0r * al0 + ls0;
    l1r = l1r * al1 + ls1;
    #pragma unroll
    for (int nt = 0; nt < 8; nt++) {
      O[nt][0] *= al0; O[nt][1] *= al0;
      O[nt][2] *= al1; O[nt][3] *= al1;
    }

    // O += P V (single pass)
    #pragma unroll
    for (int kc = 0; kc < 4; kc++) {
      const uint32_t a0 = pack2(S[2*kc][0],   S[2*kc][1]);
      const uint32_t a1 = pack2(S[2*kc][2],   S[2*kc][3]);
      const uint32_t a2 = pack2(S[2*kc+1][0], S[2*kc+1][1]);
      const uint32_t a3 = pack2(S[2*kc+1][2], S[2*kc+1][3]);
      const int kc16 = kc * 16;
      #pragma unroll
      for (int np = 0; np < 4; np++) {
        uint32_t vh[4];
        const uint32_t voff = (uint32_t)(((np * 16 + b_row) * 72 + kc16 + b_col) * 2);
        ldsm4(tVh + voff, vh);
        #pragma unroll
        for (int j = 0; j < 2; j++)
          mma_f16(O[np * 2 + j], a0, a1, a2, a3, vh[2*j], vh[2*j+1]);
      }
    }
    if (jb + 1 < nb) {
      if (jb + 2 < nb) cp_wait<1>(); else cp_wait<0>();
      __syncthreads();
    }
  }

  // epilogue
  const float inv0 = 1.f / l0r, inv1 = 1.f / l1r;
  const int colb = (bh & 15) * DH;
  const size_t orow0 = (size_t)(bh >> 4) * TT + row0g;
  const size_t orow1 = orow0 + 8;
  #pragma unroll
  for (int nd = 0; nd < 8; nd++) {
    const int d0 = nd * 8 + 2 * q;
    __half2* p0 = (__half2*)&g_Ah[orow0 * EE + colb + d0];
    __half2* p1 = (__half2*)&g_Ah[orow1 * EE + colb + d0];
    *p0 = __floats2half2_rn(O[nd][0] * inv0, O[nd][1] * inv0);
    *p1 = __floats2half2_rn(O[nd][2] * inv1, O[nd][3] * inv1);
  }
}

// ---------------------------------------------------------------------------
extern "C" void kernel_launch(void* const* d_in, const int* in_sizes, int n_in,
                              void* d_out, int out_size) {
  const float* x  = (const float*)d_in[0];
  const float* Wq = (const float*)d_in[1];
  const float* Wk = (const float*)d_in[2];
  const float* Wv = (const float*)d_in[3];
  const float* Wo = (const float*)d_in[4];
  const float* wb = (const float*)d_in[5];
  float* out = (float*)d_out;

  __half *xh, *wth, *woh, *ah;
  cudaGetSymbolAddress((void**)&xh, g_xh);
  cudaGetSymbolAddress((void**)&wth, g_Wth);
  cudaGetSymbolAddress((void**)&woh, g_Woh);
  cudaGetSymbolAddress((void**)&ah, g_Ah);

  cudaFuncSetAttribute(gemm_f16<0>, cudaFuncAttributeMaxDynamicSharedMemorySize, GEMM_SMEM);
  cudaFuncSetAttribute(gemm_f16<1>, cudaFuncAttributeMaxDynamicSharedMemorySize, GEMM_SMEM);
  cudaFuncSetAttribute(attn_f16, cudaFuncAttributeMaxDynamicSharedMemorySize, ATT_SMEM);

  conv_h<<<(MTOT*EE/4 + 255)/256, 256>>>(x, xh, MTOT*EE/4);
  conv_h<<<(EE*EE/4 + 255)/256, 256>>>(Wo, woh, EE*EE/4);
  transpose_w<<<dim3(EE/32, DH/32, 48), dim3(32, 8)>>>(Wq, Wk, Wv);

  gemm_f16<0><<<dim3(3*EE/128, MTOT/128), 256, GEMM_SMEM>>>(xh, wth, nullptr, nullptr);

  attn_f16<<<dim3(TT/128, BHN), 256, ATT_SMEM>>>();

  gemm_f16<1><<<dim3(EE/128, MTOT/128), 256, GEMM_SMEM>>>(ah, woh, wb, out);
}

// round 12
// speedup vs baseline: 6.7324x; 1.1176x over previous
#include <cuda_runtime.h>
#include <cuda_fp16.h>
#include <cstdint>

#define BB 2
#define TT 2048
#define EE 1024
#define HH 16
#define DH 64
#define MTOT (BB*TT)   // 4096
#define BHN (BB*HH)    // 32

// ---------------------------------------------------------------------------
// Global scratch. All operands fp16-rounded (error model calibrated R5-R11).
// ---------------------------------------------------------------------------
__device__ __align__(128) __half g_xh[(size_t)MTOT*EE];
__device__ __align__(128) __half g_Wth[(size_t)3*EE*EE];   // [3072][1024]
__device__ __align__(128) __half g_Qh[(size_t)BHN*TT*DH];  // [bh][t][d] (x0.125)
__device__ __align__(128) __half g_Kh[(size_t)BHN*TT*DH];  // [bh][t][d]
__device__ __align__(128) __half g_Vt[(size_t)BHN*TT*DH];  // [bh][d][t]
__device__ __align__(128) __half g_Ah[(size_t)MTOT*EE];    // attn out
__device__ __align__(128) __half g_Woh[(size_t)EE*EE];     // [out][in]

// ---------------------------------------------------------------------------
// Helpers
// ---------------------------------------------------------------------------
__device__ __forceinline__ uint32_t smem_u32(const void* p) {
  uint32_t a;
  asm("{ .reg .u64 t; cvta.to.shared.u64 t, %1; cvt.u32.u64 %0, t; }" : "=r"(a) : "l"(p));
  return a;
}
__device__ __forceinline__ void ldsm4(uint32_t addr, uint32_t r[4]) {
  asm volatile("ldmatrix.sync.aligned.m8n8.x4.shared.b16 {%0,%1,%2,%3}, [%4];"
               : "=r"(r[0]), "=r"(r[1]), "=r"(r[2]), "=r"(r[3]) : "r"(addr));
}
__device__ __forceinline__ void cp16(uint32_t dst, const void* src) {
  asm volatile("cp.async.ca.shared.global [%0], [%1], 16;" :: "r"(dst), "l"(src) : "memory");
}
__device__ __forceinline__ void cp_commit() {
  asm volatile("cp.async.commit_group;" ::: "memory");
}
template<int N> __device__ __forceinline__ void cp_wait() {
  asm volatile("cp.async.wait_group %0;" :: "n"(N) : "memory");
}
__device__ __forceinline__ uint32_t pack2(float a, float b) {  // a -> low half
  __half2 h = __floats2half2_rn(a, b);
  return *(uint32_t*)&h;
}
__device__ __forceinline__ void mma_f16(float c[4], uint32_t a0, uint32_t a1,
                                        uint32_t a2, uint32_t a3,
                                        uint32_t b0, uint32_t b1) {
  asm volatile(
    "mma.sync.aligned.m16n8k16.row.col.f32.f16.f16.f32 "
    "{%0,%1,%2,%3},{%4,%5,%6,%7},{%8,%9},{%0,%1,%2,%3};"
    : "+f"(c[0]), "+f"(c[1]), "+f"(c[2]), "+f"(c[3])
    : "r"(a0), "r"(a1), "r"(a2), "r"(a3), "r"(b0), "r"(b1));
}

// ---------------------------------------------------------------------------
// Fused conversion: x -> g_xh, Wo -> g_Woh in one launch
// ---------------------------------------------------------------------------
#define NX4 (MTOT*EE/4)
#define NW4 (EE*EE/4)
__global__ __launch_bounds__(256) void conv_both(const float* __restrict__ x,
                                                 const float* __restrict__ wo) {
  int i = blockIdx.x * 256 + threadIdx.x;
  const float* s;
  __half* H;
  int j;
  if (i < NX4)            { s = x;  H = g_xh;  j = i; }
  else if (i < NX4 + NW4) { s = wo; H = g_Woh; j = i - NX4; }
  else return;
  float4 v = ((const float4*)s)[j];
  __half2* Hp = (__half2*)(H + (size_t)j*4);
  Hp[0] = __floats2half2_rn(v.x, v.y);
  Hp[1] = __floats2half2_rn(v.z, v.w);
}

// ---------------------------------------------------------------------------
// Weight transpose (QKV): g_Wth[(p*16+h)*64 + d][e] = W_p[h][e][d]
// ---------------------------------------------------------------------------
__global__ __launch_bounds__(256) void transpose_w(
    const float* __restrict__ Wq, const float* __restrict__ Wk,
    const float* __restrict__ Wv) {
  __shared__ float t[32][33];
  const int bz = blockIdx.z;
  const int p = bz >> 4;
  const float* W = (p == 0 ? Wq : p == 1 ? Wk : Wv) + (size_t)(bz & 15) * EE * DH;
  const int e0 = blockIdx.x * 32;
  const int d0 = blockIdx.y * 32;
  const int tx = threadIdx.x, ty = threadIdx.y;
  #pragma unroll
  for (int i = ty; i < 32; i += 8)
    t[i][tx] = W[(size_t)(e0 + i) * DH + d0 + tx];
  __syncthreads();
  #pragma unroll
  for (int i = ty; i < 32; i += 8)
    g_Wth[(size_t)(bz * DH + d0 + i) * EE + e0 + tx] = __float2half_rn(t[tx][i]);
}

// ---------------------------------------------------------------------------
// fp16 GEMM. BM=128 BN=128, BK=64 per stage, 2 stages, 16 barriers total.
// ---------------------------------------------------------------------------
#define NKIT64 (EE / 64)              // 16
#define G_TILE_H 9216                 // halves per 128x72 tile (64k + 8 pad)
#define G_STAGE_B (2 * G_TILE_H * 2)  // 36864 bytes (A,B)
#define GEMM_SMEM (2 * G_STAGE_B)     // 73728

template<int MODE>
__global__ __launch_bounds__(256, 2) void gemm_f16(
    const __half* __restrict__ pAh, const __half* __restrict__ pBh,
    const float* __restrict__ bias, float* __restrict__ outp) {
  extern __shared__ __align__(16) char gsm[];
  const int tid = threadIdx.x;
  const int lane = tid & 31, q = lane & 3, g = lane >> 2;
  const int wid = tid >> 5, wm = wid >> 2, wn = wid & 3;
  const int n0 = blockIdx.x * 128;
  const size_t m0 = (size_t)blockIdx.y * 128;
  const uint32_t s0 = smem_u32(gsm);

  const int a_row = lane & 15;
  const int a_col = (lane >> 4) << 3;
  const int b_row = (lane & 7) + ((lane >> 4) << 3);
  const int b_col = ((lane >> 3) & 1) << 3;

  float C[4][4][4];
  #pragma unroll
  for (int a = 0; a < 4; a++)
    #pragma unroll
    for (int b = 0; b < 4; b++)
      #pragma unroll
      for (int c = 0; c < 4; c++) C[a][b][c] = 0.f;

  auto issue = [&](int stage, int k0) {
    const uint32_t sb = s0 + (uint32_t)stage * G_STAGE_B;
    #pragma unroll
    for (int t = 0; t < 8; t++) {
      int c = tid + t * 256;                // 0..2047
      int arr = c >> 10, rem = c & 1023;
      int row = rem >> 3, seg = rem & 7;    // 128 rows x 8 segs of 8 halves
      const __half* src = arr ? pBh + (size_t)(n0 + row) * EE + k0 + seg * 8
                              : pAh + (m0 + row) * EE + k0 + seg * 8;
      cp16(sb + (uint32_t)(arr * G_TILE_H + row * 72 + seg * 8) * 2, src);
    }
    cp_commit();
  };

  issue(0, 0);
  issue(1, 64);
  cp_wait<1>(); __syncthreads();

  for (int i = 0; i < NKIT64; i++) {
    const uint32_t sb = s0 + (uint32_t)(i & 1) * G_STAGE_B;
    const uint32_t tAh = sb, tBh = sb + G_TILE_H*2;
    #pragma unroll
    for (int kc = 0; kc < 4; kc++) {
      const int kc16 = kc * 16;
      uint32_t ah[4][4];
      #pragma unroll
      for (int mt = 0; mt < 4; mt++) {
        const uint32_t off = (uint32_t)(((wm * 64 + mt * 16 + a_row) * 72 + kc16 + a_col) * 2);
        ldsm4(tAh + off, ah[mt]);
      }
      uint32_t bhf[2][4];
      #pragma unroll
      for (int np = 0; np < 2; np++) {
        const uint32_t off = (uint32_t)(((wn * 32 + np * 16 + b_row) * 72 + kc16 + b_col) * 2);
        ldsm4(tBh + off, bhf[np]);
      }
      #pragma unroll
      for (int np = 0; np < 2; np++) {
        #pragma unroll
        for (int j = 0; j < 2; j++) {
          const int nt = np * 2 + j;
          #pragma unroll
          for (int mt = 0; mt < 4; mt++)
            mma_f16(C[mt][nt], ah[mt][0], ah[mt][1], ah[mt][2], ah[mt][3],
                    bhf[np][2*j], bhf[np][2*j+1]);
        }
      }
    }
    if (i + 1 < NKIT64) {
      cp_wait<0>(); __syncthreads();                 // stage i+1 ready, stage i free
      if (i + 2 < NKIT64) issue(i & 1, (i + 2) * 64);
    }
  }

  // epilogue
  #pragma unroll
  for (int mt = 0; mt < 4; mt++) {
    #pragma unroll
    for (int nt = 0; nt < 4; nt++) {
      #pragma unroll
      for (int e = 0; e < 4; e++) {
        const int r = (int)m0 + wm * 64 + mt * 16 + g + (e >= 2 ? 8 : 0);
        const int c = n0 + wn * 32 + nt * 8 + 2 * q + (e & 1);
        const float v = C[mt][nt][e];
        if (MODE == 0) {
          const int p = c >> 10, rl = c & 1023, hh = rl >> 6, d = rl & 63;
          const int bhi = (r >> 11) * HH + hh, t = r & (TT - 1);
          if (p == 2) {
            g_Vt[((size_t)bhi * DH + d) * TT + t] = __float2half_rn(v);
          } else if (p == 1) {
            g_Kh[((size_t)bhi * TT + t) * DH + d] = __float2half_rn(v);
          } else {
            g_Qh[((size_t)bhi * TT + t) * DH + d] = __float2half_rn(v * 0.125f);
          }
        } else {
          outp[(size_t)r * EE + c] = v + bias[c];
        }
      }
    }
  }
}

// ---------------------------------------------------------------------------
// fp16 flash attention. 128-key stages (K[128][72] + 2x V[64][72]), 2 stages,
// one barrier per 128 keys. Inner 64-key softmax/MMA identical to R11.
// ---------------------------------------------------------------------------
#define AT_Q_H    9216                 // 128*72
#define AT_T_H    4608                 // 64*72
#define AT_ST_H   (4 * AT_T_H)         // K(2x64 rows) + 2x V = 18432 halves
#define ATT_SMEM  ((AT_Q_H + 2 * AT_ST_H) * 2)   // 92160 bytes

__global__ __launch_bounds__(256, 2) void attn_f16() {
  extern __shared__ __align__(16) char asm_[];
  const int tid = threadIdx.x;
  const int lane = tid & 31, q = lane & 3, g = lane >> 2;
  const int wid = tid >> 5;
  const int i0 = ((int)gridDim.x - 1 - (int)blockIdx.x) * 128;  // heavy CTAs first
  const int bh = blockIdx.y;
  const uint32_t s0 = smem_u32(asm_);
  const uint32_t pQh = s0;
  const uint32_t kvBase = s0 + AT_Q_H * 2;

  const int a_row = lane & 15;
  const int a_col = (lane >> 4) << 3;
  const int b_row = (lane & 7) + ((lane >> 4) << 3);
  const int b_col = ((lane >> 3) & 1) << 3;

  // Q (joins KV group 0)
  #pragma unroll
  for (int t = 0; t < 4; t++) {
    int c = tid + t * 256;
    int row = c >> 3, seg = c & 7;
    const __half* src = g_Qh + ((size_t)bh * TT + i0 + row) * DH + seg * 8;
    cp16(pQh + (uint32_t)(row * 72 + seg * 8) * 2, src);
  }
  // Stage layout (halves): K rows 0..127 at 0; V sub0 at 2*AT_T_H; V sub1 at 3*AT_T_H
  auto issue_kv = [&](int stage, int j0) {
    const uint32_t kb = kvBase + (uint32_t)stage * AT_ST_H * 2;
    #pragma unroll
    for (int t = 0; t < 8; t++) {
      int c = tid + t * 256;                // 0..2047
      int arr = c >> 10;                    // 0 = K, 1 = V
      int rem = c & 1023;
      if (arr == 0) {
        int row = rem >> 3, seg = rem & 7;  // 128 key rows
        cp16(kb + (uint32_t)(row * 72 + seg * 8) * 2,
             g_Kh + ((size_t)bh * TT + j0 + row) * DH + seg * 8);
      } else {
        int sub = rem >> 9, rem2 = rem & 511;
        int drow = rem2 >> 3, seg = rem2 & 7;   // 64 d rows x 8 segs
        cp16(kb + (uint32_t)((2 + sub) * AT_T_H + drow * 72 + seg * 8) * 2,
             g_Vt + ((size_t)bh * DH + drow) * TT + j0 + sub * 64 + seg * 8);
      }
    }
    cp_commit();
  };

  const int nb = i0 / 128 + 1;
  issue_kv(0, 0);
  if (nb > 1) { issue_kv(1, 128); cp_wait<1>(); }
  else        cp_wait<0>();
  __syncthreads();

  float O[8][4];
  #pragma unroll
  for (int a = 0; a < 8; a++)
    #pragma unroll
    for (int e = 0; e < 4; e++) O[a][e] = 0.f;
  float m0r = -1e30f, m1r = -1e30f, l0r = 0.f, l1r = 0.f;
  const int row0g = i0 + wid * 16 + g;
  const int row1g = row0g + 8;

  for (int jb = 0; jb < nb; jb++) {
    const uint32_t kb = kvBase + (uint32_t)(jb & 1) * AT_ST_H * 2;
    #pragma unroll
    for (int sb = 0; sb < 2; sb++) {
      const int j0 = jb * 128 + sb * 64;
      const uint32_t tKh = kb + (uint32_t)(sb * 64 * 72) * 2;
      const uint32_t tVh = kb + (uint32_t)((2 + sb) * AT_T_H) * 2;

      // S = Q K^T
      float S[8][4];
      #pragma unroll
      for (int a = 0; a < 8; a++)
        #pragma unroll
        for (int e = 0; e < 4; e++) S[a][e] = 0.f;
      #pragma unroll
      for (int kc = 0; kc < 4; kc++) {
        const int kc16 = kc * 16;
        uint32_t qh[4];
        const uint32_t qoff = (uint32_t)(((wid * 16 + a_row) * 72 + kc16 + a_col) * 2);
        ldsm4(pQh + qoff, qh);
        #pragma unroll
        for (int np = 0; np < 4; np++) {
          uint32_t kh[4];
          const uint32_t koff = (uint32_t)(((np * 16 + b_row) * 72 + kc16 + b_col) * 2);
          ldsm4(tKh + koff, kh);
          #pragma unroll
          for (int j = 0; j < 2; j++)
            mma_f16(S[np * 2 + j], qh[0], qh[1], qh[2], qh[3], kh[2*j], kh[2*j+1]);
        }
      }

      // causal mask (scale folded into Q)
      if (j0 >= i0) {
        #pragma unroll
        for (int nt = 0; nt < 8; nt++) {
          const int cb = j0 + nt * 8 + 2 * q;
          if (cb     > row0g) S[nt][0] = -1e30f;
          if (cb + 1 > row0g) S[nt][1] = -1e30f;
          if (cb     > row1g) S[nt][2] = -1e30f;
          if (cb + 1 > row1g) S[nt][3] = -1e30f;
        }
      }

      // online softmax
      float mx0 = -1e30f, mx1 = -1e30f;
      #pragma unroll
      for (int nt = 0; nt < 8; nt++) {
        mx0 = fmaxf(mx0, fmaxf(S[nt][0], S[nt][1]));
        mx1 = fmaxf(mx1, fmaxf(S[nt][2], S[nt][3]));
      }
      mx0 = fmaxf(mx0, __shfl_xor_sync(0xffffffffu, mx0, 1));
      mx0 = fmaxf(mx0, __shfl_xor_sync(0xffffffffu, mx0, 2));
      mx1 = fmaxf(mx1, __shfl_xor_sync(0xffffffffu, mx1, 1));
      mx1 = fmaxf(mx1, __shfl_xor_sync(0xffffffffu, mx1, 2));
      const float mn0 = fmaxf(m0r, mx0), mn1 = fmaxf(m1r, mx1);
      const float al0 = __expf(m0r - mn0), al1 = __expf(m1r - mn1);
      m0r = mn0; m1r = mn1;
      float ls0 = 0.f, ls1 = 0.f;
      #pragma unroll
      for (int nt = 0; nt < 8; nt++) {
        S[nt][0] = __expf(S[nt][0] - mn0); ls0 += S[nt][0];
        S[nt][1] = __expf(S[nt][1] - mn0); ls0 += S[nt][1];
        S[nt][2] = __expf(S[nt][2] - mn1); ls1 += S[nt][2];
        S[nt][3] = __expf(S[nt][3] - mn1); ls1 += S[nt][3];
      }
      ls0 += __shfl_xor_sync(0xffffffffu, ls0, 1);
      ls0 += __shfl_xor_sync(0xffffffffu, ls0, 2);
      ls1 += __shfl_xor_sync(0xffffffffu, ls1, 1);
      ls1 += __shfl_xor_sync(0xffffffffu, ls1, 2);
      l0r = l0r * al0 + ls0;
      l1r = l1r * al1 + ls1;
      #pragma unroll
      for (int nt = 0; nt < 8; nt++) {
        O[nt][0] *= al0; O[nt][1] *= al0;
        O[nt][2] *= al1; O[nt][3] *= al1;
      }

      // O += P V
      #pragma unroll
      for (int kc = 0; kc < 4; kc++) {
        const uint32_t a0 = pack2(S[2*kc][0],   S[2*kc][1]);
        const uint32_t a1 = pack2(S[2*kc][2],   S[2*kc][3]);
        const uint32_t a2 = pack2(S[2*kc+1][0], S[2*kc+1][1]);
        const uint32_t a3 = pack2(S[2*kc+1][2], S[2*kc+1][3]);
        const int kc16 = kc * 16;
        #pragma unroll
        for (int np = 0; np < 4; np++) {
          uint32_t vh[4];
          const uint32_t voff = (uint32_t)(((np * 16 + b_row) * 72 + kc16 + b_col) * 2);
          ldsm4(tVh + voff, vh);
          #pragma unroll
          for (int j = 0; j < 2; j++)
            mma_f16(O[np * 2 + j], a0, a1, a2, a3, vh[2*j], vh[2*j+1]);
        }
      }
    }
    if (jb + 1 < nb) {
      cp_wait<0>(); __syncthreads();
      if (jb + 2 < nb) issue_kv(jb & 1, (jb + 2) * 128);
    }
  }

  // epilogue
  const float inv0 = 1.f / l0r, inv1 = 1.f / l1r;
  const int colb = (bh & 15) * DH;
  const size_t orow0 = (size_t)(bh >> 4) * TT + row0g;
  const size_t orow1 = orow0 + 8;
  #pragma unroll
  for (int nd = 0; nd < 8; nd++) {
    const int d0 = nd * 8 + 2 * q;
    __half2* p0 = (__half2*)&g_Ah[orow0 * EE + colb + d0];
    __half2* p1 = (__half2*)&g_Ah[orow1 * EE + colb + d0];
    *p0 = __floats2half2_rn(O[nd][0] * inv0, O[nd][1] * inv0);
    *p1 = __floats2half2_rn(O[nd][2] * inv1, O[nd][3] * inv1);
  }
}

// ---------------------------------------------------------------------------
extern "C" void kernel_launch(void* const* d_in, const int* in_sizes, int n_in,
                              void* d_out, int out_size) {
  const float* x  = (const float*)d_in[0];
  const float* Wq = (const float*)d_in[1];
  const float* Wk = (const float*)d_in[2];
  const float* Wv = (const float*)d_in[3];
  const float* Wo = (const float*)d_in[4];
  const float* wb = (const float*)d_in[5];
  float* out = (float*)d_out;

  __half *xh, *wth, *woh, *ah;
  cudaGetSymbolAddress((void**)&xh, g_xh);
  cudaGetSymbolAddress((void**)&wth, g_Wth);
  cudaGetSymbolAddress((void**)&woh, g_Woh);
  cudaGetSymbolAddress((void**)&ah, g_Ah);

  cudaFuncSetAttribute(gemm_f16<0>, cudaFuncAttributeMaxDynamicSharedMemorySize, GEMM_SMEM);
  cudaFuncSetAttribute(gemm_f16<1>, cudaFuncAttributeMaxDynamicSharedMemorySize, GEMM_SMEM);
  cudaFuncSetAttribute(attn_f16, cudaFuncAttributeMaxDynamicSharedMemorySize, ATT_SMEM);

  conv_both<<<(NX4 + NW4 + 255)/256, 256>>>(x, Wo);
  transpose_w<<<dim3(EE/32, DH/32, 48), dim3(32, 8)>>>(Wq, Wk, Wv);

  gemm_f16<0><<<dim3(3*EE/128, MTOT/128), 256, GEMM_SMEM>>>(xh, wth, nullptr, nullptr);

  attn_f16<<<dim3(TT/128, BHN), 256, ATT_SMEM>>>();

  gemm_f16<1><<<dim3(EE/128, MTOT/128), 256, GEMM_SMEM>>>(ah, woh, wb, out);
}